// round 13
// baseline (speedup 1.0000x reference)
#include <cuda_runtime.h>
#include <cuda_fp16.h>
#include <math.h>
#include <stdint.h>

#define BSZ 2
#define SEQ 2048
#define DD 1024
#define CH 128
#define NCH 16
#define MTOT (BSZ*SEQ)        // 4096
#define EPSV 1e-6f

typedef __half hf;

// ---------------- scratch ----------------
__device__ float d_memout[MTOT*DD];              // g*act*memout/normq
__device__ float d_zz[BSZ*NCH*DD];
__device__ float d_den[BSZ*NCH*CH];
__device__ float d_scal[2];

// fp16 operand buffers
__device__ hf d_hsh[MTOT*DD];
__device__ hf d_wqh[DD*DD];
__device__ hf d_wkh[DD*DD];
__device__ hf d_wvh[DD*DD];
__device__ hf d_woh[DD*DD];
__device__ hf d_memTh[DD*DD];
__device__ hf d_sqh[MTOT*DD];
__device__ hf d_skh[MTOT*DD];
__device__ hf d_vh [MTOT*DD];
__device__ hf d_Gh [(size_t)BSZ*NCH*DD*DD];      // per-chunk KV products
__device__ hf d_Sph[(size_t)BSZ*NCH*DD*DD];      // exclusive prefix of G
__device__ hf d_Abh[BSZ*NCH*CH*CH];
__device__ hf d_cmh[MTOT*DD];

// ---------------- small kernels ----------------
__global__ void scalars_kernel(const float* __restrict__ gate,
                               const float* __restrict__ mnorm) {
    __shared__ float sh[1024];
    int t = threadIdx.x;
    sh[t] = mnorm[t];
    __syncthreads();
    for (int s = 512; s > 0; s >>= 1) { if (t < s) sh[t] += sh[t+s]; __syncthreads(); }
    if (t == 0) {
        d_scal[0] = 1.f / (1.f + expf(-gate[0]));
        d_scal[1] = (sh[0] >= EPSV) ? 1.f : 0.f;
    }
}

__device__ __forceinline__ void cvt4hi(const float4* src, uint2* hi, int i) {
    float4 x = src[i];
    union { __half2 b[2]; uint2 u; } uh;
    uh.b[0] = __halves2half2(__float2half_rn(x.x), __float2half_rn(x.y));
    uh.b[1] = __halves2half2(__float2half_rn(x.z), __float2half_rn(x.w));
    hi[i] = uh.u;
}

// fused converts: hs | wq | wk | wv | wo | memT
__global__ void cvt_all(const float4* __restrict__ hs,
                        const float4* __restrict__ wq, const float4* __restrict__ wk,
                        const float4* __restrict__ wv, const float4* __restrict__ wo,
                        const float* __restrict__ mem) {
    int bid = blockIdx.x, tid = threadIdx.x;
    if (bid < 4096)        cvt4hi(hs, (uint2*)d_hsh, bid*256 + tid);
    else if (bid < 5120)   cvt4hi(wq, (uint2*)d_wqh, (bid-4096)*256 + tid);
    else if (bid < 6144)   cvt4hi(wk, (uint2*)d_wkh, (bid-5120)*256 + tid);
    else if (bid < 7168)   cvt4hi(wv, (uint2*)d_wvh, (bid-6144)*256 + tid);
    else if (bid < 8192)   cvt4hi(wo, (uint2*)d_woh, (bid-7168)*256 + tid);
    else {
        int idx = (bid-8192)*256 + tid;           // DD*DD
        int k = idx & (DD-1), n = idx >> 10;
        d_memTh[(size_t)n*DD + k] = __float2half_rn(mem[(size_t)k*DD + n]);
    }
}

// ---------------- tensor-core GEMM core (pure fp16, K-step 32, 3-stage) ----------------
#define NT_STRIDE 40
#define T_STRIDE 136
#define MAT_B 10240
#define STAGE_B (2*MAT_B)     // A + B = 20480
#define SMEM_TOT (3*STAGE_B)  // 61440

__device__ __forceinline__ void cpa16(void* dst, const void* src) {
    uint32_t d = (uint32_t)__cvta_generic_to_shared(dst);
    asm volatile("cp.async.cg.shared.global [%0], [%1], 16;" :: "r"(d), "l"(src));
}
__device__ __forceinline__ void cp_commit() { asm volatile("cp.async.commit_group;"); }
__device__ __forceinline__ void cp_wait1()  { asm volatile("cp.async.wait_group 1;"); }
__device__ __forceinline__ void cp_wait0()  { asm volatile("cp.async.wait_group 0;"); }

__device__ __forceinline__ void ldsm4a(uint32_t* r, uint32_t a) {
    asm volatile("ldmatrix.sync.aligned.m8n8.x4.shared.b16 {%0,%1,%2,%3}, [%4];"
        : "=r"(r[0]), "=r"(r[1]), "=r"(r[2]), "=r"(r[3]) : "r"(a));
}
__device__ __forceinline__ void ldsm4ta(uint32_t* r, uint32_t a) {
    asm volatile("ldmatrix.sync.aligned.m8n8.x4.trans.shared.b16 {%0,%1,%2,%3}, [%4];"
        : "=r"(r[0]), "=r"(r[1]), "=r"(r[2]), "=r"(r[3]) : "r"(a));
}
__device__ __forceinline__ void mma_f16(float* c, const uint32_t* a, const uint32_t* b) {
    asm volatile("mma.sync.aligned.m16n8k16.row.col.f32.f16.f16.f32 "
        "{%0,%1,%2,%3}, {%4,%5,%6,%7}, {%8,%9}, {%0,%1,%2,%3};"
        : "+f"(c[0]), "+f"(c[1]), "+f"(c[2]), "+f"(c[3])
        : "r"(a[0]), "r"(a[1]), "r"(a[2]), "r"(a[3]), "r"(b[0]), "r"(b[1]));
}

struct Op { const hf* p; int ld; };

template<int TA, int TB>
__device__ __forceinline__ void stage(Op A, Op B, int k0, char* sm, int tid) {
    hf* Ah = (hf*)sm;
    hf* Bh = (hf*)(sm + MAT_B);
    #pragma unroll
    for (int i = 0; i < 2; ++i) {
        int idx = tid + 256*i;
        if (!TA) {
            int row = idx >> 2, ch = idx & 3;
            cpa16(Ah + row*NT_STRIDE + ch*8, A.p + (size_t)row*A.ld + k0 + ch*8);
        } else {
            int row = idx >> 4, ch = idx & 15;
            cpa16(Ah + row*T_STRIDE + ch*8, A.p + (size_t)(k0 + row)*A.ld + ch*8);
        }
        if (!TB) {
            int row = idx >> 2, ch = idx & 3;
            cpa16(Bh + row*NT_STRIDE + ch*8, B.p + (size_t)row*B.ld + k0 + ch*8);
        } else {
            int row = idx >> 4, ch = idx & 15;
            cpa16(Bh + row*T_STRIDE + ch*8, B.p + (size_t)(k0 + row)*B.ld + ch*8);
        }
    }
}

struct LaneOff {
    uint32_t a[2];
    uint32_t b[4];
};
template<int TA, int TB>
__device__ __forceinline__ LaneOff make_off(int lane, int wm, int wn) {
    LaneOff lo;
    #pragma unroll
    for (int mt = 0; mt < 2; ++mt) {
        lo.a[mt] = (!TA)
            ? (uint32_t)(((wm + mt*16 + (lane & 15))*NT_STRIDE + ((lane >> 4) << 3)) * 2)
            : (uint32_t)(((((lane >> 4) << 3) + (lane & 7))*T_STRIDE + wm + mt*16 + (lane & 8)) * 2);
    }
    #pragma unroll
    for (int nq = 0; nq < 4; ++nq) {
        lo.b[nq] = (!TB)
            ? (uint32_t)(MAT_B + ((wn + nq*16 + (lane & 15))*NT_STRIDE + ((lane >> 4) << 3)) * 2)
            : (uint32_t)(MAT_B + (((lane & 15))*T_STRIDE + wn + nq*16 + ((lane >> 4) << 3)) * 2);
    }
    return lo;
}

template<int TA, int TB>
__device__ __forceinline__ void compute16(uint32_t smaddr, int ks, const LaneOff& lo,
                                          float acc[2][8][4]) {
    const uint32_t dA = (!TA) ? (uint32_t)(2*ks) : (uint32_t)(2*ks*T_STRIDE);
    const uint32_t dB = (!TB) ? (uint32_t)(2*ks) : (uint32_t)(2*ks*T_STRIDE);
    uint32_t ah[2][4], bh[8][2];
    #pragma unroll
    for (int mt = 0; mt < 2; ++mt) {
        uint32_t a = smaddr + lo.a[mt] + dA;
        if (!TA) ldsm4a(ah[mt], a); else ldsm4ta(ah[mt], a);
    }
    #pragma unroll
    for (int nq = 0; nq < 4; ++nq) {
        uint32_t a = smaddr + lo.b[nq] + dB;
        uint32_t r[4];
        if (!TB) {
            ldsm4a(r, a);
            bh[2*nq][0]=r[0]; bh[2*nq][1]=r[2]; bh[2*nq+1][0]=r[1]; bh[2*nq+1][1]=r[3];
        } else {
            ldsm4ta(r, a);
            bh[2*nq][0]=r[0]; bh[2*nq][1]=r[1]; bh[2*nq+1][0]=r[2]; bh[2*nq+1][1]=r[3];
        }
    }
    #pragma unroll
    for (int mt = 0; mt < 2; ++mt)
        #pragma unroll
        for (int nt = 0; nt < 8; ++nt)
            mma_f16(acc[mt][nt], ah[mt], bh[nt]);
}

// 3-stage pipeline: prefetch 2 tiles ahead, one __syncthreads per k-iter.
template<int TA, int TB>
__device__ __forceinline__ void gemm_core(Op A, Op B, int K, float acc[2][8][4],
                                          char* smbase, int tid) {
    const int lane = tid & 31, wid = tid >> 5;
    const int wm = (wid & 3) * 32, wn = (wid >> 2) * 64;
    const LaneOff lo = make_off<TA,TB>(lane, wm, wn);
    const uint32_t base0 = (uint32_t)__cvta_generic_to_shared(smbase);
    const int KT = K >> 5;   // >= 4 always
    stage<TA,TB>(A, B, 0, smbase, tid);            cp_commit();
    stage<TA,TB>(A, B, 32, smbase + STAGE_B, tid); cp_commit();
    int buf = 0;
    for (int kt = 0; kt < KT; ++kt) {
        if (kt + 1 < KT) cp_wait1(); else cp_wait0();
        __syncthreads();
        uint32_t cur = base0 + (uint32_t)(buf*STAGE_B);
        compute16<TA,TB>(cur, 0,  lo, acc);
        compute16<TA,TB>(cur, 16, lo, acc);
        if (kt + 2 < KT) {
            int nb = buf + 2; if (nb >= 3) nb -= 3;
            stage<TA,TB>(A, B, (kt+2) << 5, smbase + nb*STAGE_B, tid);
            cp_commit();
        }
        buf = (buf + 1 == 3) ? 0 : buf + 1;
    }
    __syncthreads();
}

#define GEMM_SMEM extern __shared__ char sm_[];

#define EPI_COORDS \
    const int lane = tid & 31, wid = tid >> 5; \
    const int gid = lane >> 2, tig = lane & 3; \
    const int wm = (wid & 3) * 32, wn = (wid >> 2) * 64;

#define EPI_LOOP(BODY) \
    _Pragma("unroll") for (int mt = 0; mt < 2; ++mt) \
    _Pragma("unroll") for (int nt = 0; nt < 8; ++nt) \
    _Pragma("unroll") for (int ci = 0; ci < 4; ++ci) { \
        int mr = wm + mt*16 + gid + ((ci >> 1) ? 8 : 0); \
        int nr = wn + nt*8 + tig*2 + (ci & 1); \
        float v = acc[mt][nt][ci]; \
        BODY \
    }

// ---------------- GEMM kernels ----------------
__global__ void __launch_bounds__(256, 2) tc_proj3() {
    GEMM_SMEM;
    int tid = threadIdx.x;
    int m0 = blockIdx.y * 128, n0 = blockIdx.x * 128;
    int which = blockIdx.z;
    const hf* wh = (which==0) ? d_wqh : (which==1) ? d_wkh : d_wvh;
    float acc[2][8][4] = {};
    Op A{d_hsh + (size_t)m0*DD, DD};
    Op B{wh + (size_t)n0*DD, DD};
    gemm_core<0,0>(A, B, DD, acc, sm_, tid);
    EPI_COORDS;
    if (which == 0) {
        EPI_LOOP({
            size_t o = (size_t)(m0+mr)*DD + n0 + nr;
            v = (v > 0.f) ? v + 1.f : expf(v);
            d_sqh[o] = __float2half_rn(v);
        })
    } else if (which == 1) {
        EPI_LOOP({
            size_t o = (size_t)(m0+mr)*DD + n0 + nr;
            v = (v > 0.f) ? v + 1.f : expf(v);
            d_skh[o] = __float2half_rn(v);
        })
    } else {
        EPI_LOOP({
            size_t o = (size_t)(m0+mr)*DD + n0 + nr;
            d_vh[o] = __float2half_rn(v);
        })
    }
}

// fused wave2: memout(+inline normq) 256 | kv 2048 | scores 32 | zcp 8
__global__ void __launch_bounds__(256, 2) wave2(const float* __restrict__ mnorm) {
    GEMM_SMEM;
    int tid = threadIdx.x;
    int bid = blockIdx.x;
    if (bid < 256) {
        int m0 = (bid >> 3) * 128, n0 = (bid & 7) * 128;
        float acc[2][8][4] = {};
        Op A{d_sqh + (size_t)m0*DD, DD};
        Op B{d_memTh + (size_t)n0*DD, DD};
        gemm_core<0,0>(A, B, DD, acc, sm_, tid);
        // inline normq into smem (gemm_core ended with __syncthreads)
        float* nq = (float*)sm_;
        {
            int w = tid >> 5, lane2 = tid & 31;
            for (int r = w; r < 128; r += 8) {
                const hf* row = d_sqh + (size_t)(m0 + r)*DD;
                float s = 0.f;
                for (int k = lane2; k < DD; k += 32)
                    s += __half2float(row[k]) * mnorm[k];
                #pragma unroll
                for (int o = 16; o > 0; o >>= 1) s += __shfl_xor_sync(0xffffffffu, s, o);
                if (lane2 == 0) nq[r] = fmaxf(s, EPSV);
            }
        }
        __syncthreads();
        float gs = d_scal[0] * d_scal[1];
        EPI_COORDS;
        EPI_LOOP({
            d_memout[(size_t)(m0+mr)*DD + n0 + nr] = v * gs / nq[mr];
        })
    } else if (bid < 2304) {
        int idx = bid - 256;
        int bn = idx >> 6, loc = idx & 63;
        int b = bn >> 4, n = bn & 15;
        size_t cb = (size_t)(b*SEQ + n*CH)*DD;
        int m0 = (loc >> 3) * 128, n0 = (loc & 7) * 128;
        float acc[2][8][4] = {};
        Op A{d_skh + cb + m0, DD};
        Op B{d_vh + cb + n0, DD};
        gemm_core<1,1>(A, B, CH, acc, sm_, tid);
        hf* C = d_Gh + (size_t)bn*DD*DD;
        EPI_COORDS;
        EPI_LOOP({
            C[(size_t)(m0+mr)*DD + n0 + nr] = __float2half_rn(v);
        })
    } else if (bid < 2336) {
        int bn = bid - 2304;
        int b = bn >> 4, n = bn & 15;
        size_t cb = (size_t)(b*SEQ + n*CH)*DD;
        float acc[2][8][4] = {};
        Op A{d_sqh + cb, DD};
        Op B{d_skh + cb, DD};
        gemm_core<0,0>(A, B, DD, acc, sm_, tid);
        size_t co = (size_t)bn*CH*CH;
        EPI_COORDS;
        EPI_LOOP({
            float m = (nr <= mr) ? v : 0.f;
            d_Abh[co + (size_t)mr*CH + nr] = __float2half_rn(m);
        })
    } else {
        // zcp: per-chunk colsums of sk + exclusive prefix, thread per (b,d)
        int idx = (bid - 2336)*256 + tid;    // 0..2047
        int b = idx >> 10, d = idx & (DD-1);
        float run = 0.f;
        for (int n = 0; n < NCH; ++n) {
            const hf* base = d_skh + (size_t)(b*SEQ + n*CH)*DD + d;
            float s = 0.f;
            #pragma unroll 4
            for (int i = 0; i < CH; ++i) s += __half2float(base[(size_t)i*DD]);
            d_zz[(b*NCH + n)*DD + d] = run;
            run += s;
        }
    }
}

// fused wave3: gprefix (8192 blocks) + den (512 blocks, fp16 Abh)
__global__ void __launch_bounds__(256) wave3() {
    int bid = blockIdx.x, tid = threadIdx.x;
    if (bid < 8192) {
        size_t idx = (size_t)bid*256 + tid;
        int b = (int)(idx / ((size_t)DD*DD));
        size_t rem = idx % ((size_t)DD*DD);
        float run = 0.f;
        for (int n = 0; n < NCH; ++n) {
            size_t off = ((size_t)(b*NCH + n)*DD*DD) + rem;
            float t = __half2float(d_Gh[off]);
            d_Sph[off] = __float2half_rn(run);
            run += t;
        }
    } else {
        int warp = ((bid - 8192)*256 + tid) >> 5;
        int lane = tid & 31;
        if (warp >= BSZ*NCH*CH) return;
        int bn = warp / CH, i = warp % CH;
        int b = bn >> 4, n = bn & 15;
        const hf* qr = d_sqh + (size_t)(b*SEQ + n*CH + i)*DD;
        const float* zr = d_zz + (size_t)bn*DD;
        float s = 0.f;
        for (int k = lane; k < DD; k += 32) s += __half2float(qr[k]) * zr[k];
        const hf* ar = d_Abh + (size_t)bn*CH*CH + (size_t)i*CH;
        for (int j = lane; j < CH; j += 32) s += __half2float(ar[j]);
        #pragma unroll
        for (int o = 16; o > 0; o >>= 1) s += __shfl_xor_sync(0xffffffffu, s, o);
        if (lane == 0) d_den[warp] = fmaxf(s, EPSV);
    }
}

// attn: local = (sq @ Sp + Abuf @ v)/den; epilogue fuses combine -> d_cmh
__global__ void __launch_bounds__(256, 2) tc_attn() {
    GEMM_SMEM;
    int tid = threadIdx.x;
    int bn = blockIdx.z; int b = bn >> 4, n = bn & 15;
    size_t cb = (size_t)(b*SEQ + n*CH)*DD;
    int n0 = blockIdx.x * 128;
    float acc[2][8][4] = {};
    {
        Op A{d_sqh + cb, DD};
        Op B{d_Sph + (size_t)bn*DD*DD + n0, DD};   // trans [d][e]
        gemm_core<0,1>(A, B, DD, acc, sm_, tid);
    }
    {
        Op A{d_Abh + (size_t)bn*CH*CH, CH};
        Op B{d_vh + cb + n0, DD};                  // trans [c][e]
        gemm_core<0,1>(A, B, CH, acc, sm_, tid);
    }
    float og = 1.f - d_scal[0];
    EPI_COORDS;
    EPI_LOOP({
        size_t o = cb + (size_t)mr*DD + n0 + nr;
        float cm = d_memout[o] + og * v / d_den[bn*CH + mr];
        d_cmh[o] = __float2half_rn(cm);
    })
}

__global__ void __launch_bounds__(256, 2) tc_final(float* __restrict__ Out) {
    GEMM_SMEM;
    int tid = threadIdx.x;
    int m0 = blockIdx.y * 128, n0 = blockIdx.x * 128;
    float acc[2][8][4] = {};
    Op A{d_cmh + (size_t)m0*DD, DD};
    Op B{d_woh + (size_t)n0*DD, DD};
    gemm_core<0,0>(A, B, DD, acc, sm_, tid);
    EPI_COORDS;
    EPI_LOOP({
        Out[(size_t)(m0+mr)*DD + n0 + nr] = v;
    })
}

// ---------------- launcher ----------------
extern "C" void kernel_launch(void* const* d_in, const int* in_sizes, int n_in,
                              void* d_out, int out_size) {
    const float* hs    = (const float*)d_in[0];
    const float* wq    = (const float*)d_in[1];
    const float* wk    = (const float*)d_in[2];
    const float* wv    = (const float*)d_in[3];
    const float* wo    = (const float*)d_in[4];
    const float* gate  = (const float*)d_in[5];
    const float* mem   = (const float*)d_in[6];
    const float* mnorm = (const float*)d_in[7];
    float* out = (float*)d_out;

    cudaFuncSetAttribute(tc_proj3, cudaFuncAttributeMaxDynamicSharedMemorySize, SMEM_TOT);
    cudaFuncSetAttribute(wave2,    cudaFuncAttributeMaxDynamicSharedMemorySize, SMEM_TOT);
    cudaFuncSetAttribute(tc_attn,  cudaFuncAttributeMaxDynamicSharedMemorySize, SMEM_TOT);
    cudaFuncSetAttribute(tc_final, cudaFuncAttributeMaxDynamicSharedMemorySize, SMEM_TOT);

    scalars_kernel<<<1, 1024>>>(gate, mnorm);

    cvt_all<<<12288, 256>>>((const float4*)hs, (const float4*)wq, (const float4*)wk,
                            (const float4*)wv, (const float4*)wo, mem);

    dim3 gP(DD/128, MTOT/128, 3);       // (8, 32, 3)
    tc_proj3<<<gP, 256, SMEM_TOT>>>();

    wave2<<<2344, 256, SMEM_TOT>>>(mnorm);
    wave3<<<8704, 256>>>();

    dim3 gAt(DD/128, 1, BSZ*NCH);       // (8, 1, 32)
    tc_attn<<<gAt, 256, SMEM_TOT>>>();

    dim3 gM(DD/128, MTOT/128);          // (8, 32)
    tc_final<<<gM, 256, SMEM_TOT>>>(out);
}

// round 14
// speedup vs baseline: 1.2339x; 1.2339x over previous
#include <cuda_runtime.h>
#include <cuda_fp16.h>
#include <math.h>
#include <stdint.h>

#define BSZ 2
#define SEQ 2048
#define DD 1024
#define CH 128
#define NCH 16
#define MTOT (BSZ*SEQ)        // 4096
#define EPSV 1e-6f

typedef __half hf;

// ---------------- scratch ----------------
__device__ float d_memout[MTOT*DD];              // g*act*memout/normq
__device__ float d_zz[BSZ*NCH*DD];
__device__ float d_den[BSZ*NCH*CH];
__device__ float d_normq[MTOT];
__device__ float d_scal[2];

// fp16 operand buffers
__device__ hf d_hsh[MTOT*DD];
__device__ hf d_wqh[DD*DD];
__device__ hf d_wkh[DD*DD];
__device__ hf d_wvh[DD*DD];
__device__ hf d_woh[DD*DD];
__device__ hf d_memTh[DD*DD];
__device__ hf d_sqh[MTOT*DD];
__device__ hf d_skh[MTOT*DD];
__device__ hf d_vh [MTOT*DD];
__device__ hf d_Gh [(size_t)BSZ*NCH*DD*DD];      // per-chunk KV products
__device__ hf d_Sph[(size_t)BSZ*NCH*DD*DD];      // exclusive prefix of G
__device__ hf d_Abh[BSZ*NCH*CH*CH];
__device__ hf d_cmh[MTOT*DD];

// ---------------- small kernels ----------------
__global__ void scalars_kernel(const float* __restrict__ gate,
                               const float* __restrict__ mnorm) {
    __shared__ float sh[1024];
    int t = threadIdx.x;
    sh[t] = mnorm[t];
    __syncthreads();
    for (int s = 512; s > 0; s >>= 1) { if (t < s) sh[t] += sh[t+s]; __syncthreads(); }
    if (t == 0) {
        d_scal[0] = 1.f / (1.f + expf(-gate[0]));
        d_scal[1] = (sh[0] >= EPSV) ? 1.f : 0.f;
    }
}

__device__ __forceinline__ void cvt4hi(const float4* src, uint2* hi, int i) {
    float4 x = src[i];
    union { __half2 b[2]; uint2 u; } uh;
    uh.b[0] = __halves2half2(__float2half_rn(x.x), __float2half_rn(x.y));
    uh.b[1] = __halves2half2(__float2half_rn(x.z), __float2half_rn(x.w));
    hi[i] = uh.u;
}

// fused converts: hs | wq | wk | wv | wo | memT
__global__ void cvt_all(const float4* __restrict__ hs,
                        const float4* __restrict__ wq, const float4* __restrict__ wk,
                        const float4* __restrict__ wv, const float4* __restrict__ wo,
                        const float* __restrict__ mem) {
    int bid = blockIdx.x, tid = threadIdx.x;
    if (bid < 4096)        cvt4hi(hs, (uint2*)d_hsh, bid*256 + tid);
    else if (bid < 5120)   cvt4hi(wq, (uint2*)d_wqh, (bid-4096)*256 + tid);
    else if (bid < 6144)   cvt4hi(wk, (uint2*)d_wkh, (bid-5120)*256 + tid);
    else if (bid < 7168)   cvt4hi(wv, (uint2*)d_wvh, (bid-6144)*256 + tid);
    else if (bid < 8192)   cvt4hi(wo, (uint2*)d_woh, (bid-7168)*256 + tid);
    else {
        int idx = (bid-8192)*256 + tid;           // DD*DD
        int k = idx & (DD-1), n = idx >> 10;
        d_memTh[(size_t)n*DD + k] = __float2half_rn(mem[(size_t)k*DD + n]);
    }
}

__global__ void normq_kernel(const float* __restrict__ mnorm) {
    int warp = (blockIdx.x * blockDim.x + threadIdx.x) >> 5;
    int lane = threadIdx.x & 31;
    if (warp >= MTOT) return;
    const hf* row = d_sqh + (size_t)warp * DD;
    float s = 0.f;
    for (int k = lane; k < DD; k += 32) s += __half2float(row[k]) * mnorm[k];
    #pragma unroll
    for (int o = 16; o > 0; o >>= 1) s += __shfl_xor_sync(0xffffffffu, s, o);
    if (lane == 0) d_normq[warp] = fmaxf(s, EPSV);
}

__global__ void zc_kernel() {
    int idx = blockIdx.x * blockDim.x + threadIdx.x;
    if (idx >= BSZ*NCH*DD) return;
    int d = idx % DD; int bn = idx / DD;
    int b = bn >> 4, n = bn & 15;
    const hf* base = d_skh + (size_t)(b*SEQ + n*CH)*DD + d;
    float s = 0.f;
    #pragma unroll 4
    for (int i = 0; i < CH; ++i) s += __half2float(base[(size_t)i*DD]);
    d_zz[idx] = s;
}

__global__ void zprefix_kernel() {
    int idx = blockIdx.x * blockDim.x + threadIdx.x;
    if (idx >= BSZ*DD) return;
    int b = idx / DD, d = idx % DD;
    float run = 0.f;
    for (int n = 0; n < NCH; ++n) {
        float* p = d_zz + (size_t)(b*NCH + n)*DD + d;
        float t = *p; *p = run; run += t;
    }
}

// ---------------- tensor-core GEMM core (pure fp16, K-step 32, 3-stage) ----------------
#define NT_STRIDE 40
#define T_STRIDE 136
#define MAT_B 10240
#define STAGE_B (2*MAT_B)     // A + B = 20480
#define SMEM_TOT (3*STAGE_B)  // 61440

__device__ __forceinline__ void cpa16(void* dst, const void* src) {
    uint32_t d = (uint32_t)__cvta_generic_to_shared(dst);
    asm volatile("cp.async.cg.shared.global [%0], [%1], 16;" :: "r"(d), "l"(src));
}
__device__ __forceinline__ void cp_commit() { asm volatile("cp.async.commit_group;"); }
__device__ __forceinline__ void cp_wait1()  { asm volatile("cp.async.wait_group 1;"); }
__device__ __forceinline__ void cp_wait0()  { asm volatile("cp.async.wait_group 0;"); }

__device__ __forceinline__ void ldsm4a(uint32_t* r, uint32_t a) {
    asm volatile("ldmatrix.sync.aligned.m8n8.x4.shared.b16 {%0,%1,%2,%3}, [%4];"
        : "=r"(r[0]), "=r"(r[1]), "=r"(r[2]), "=r"(r[3]) : "r"(a));
}
__device__ __forceinline__ void ldsm4ta(uint32_t* r, uint32_t a) {
    asm volatile("ldmatrix.sync.aligned.m8n8.x4.trans.shared.b16 {%0,%1,%2,%3}, [%4];"
        : "=r"(r[0]), "=r"(r[1]), "=r"(r[2]), "=r"(r[3]) : "r"(a));
}
__device__ __forceinline__ void mma_f16(float* c, const uint32_t* a, const uint32_t* b) {
    asm volatile("mma.sync.aligned.m16n8k16.row.col.f32.f16.f16.f32 "
        "{%0,%1,%2,%3}, {%4,%5,%6,%7}, {%8,%9}, {%0,%1,%2,%3};"
        : "+f"(c[0]), "+f"(c[1]), "+f"(c[2]), "+f"(c[3])
        : "r"(a[0]), "r"(a[1]), "r"(a[2]), "r"(a[3]), "r"(b[0]), "r"(b[1]));
}

struct Op { const hf* p; int ld; };

template<int TA, int TB>
__device__ __forceinline__ void stage(Op A, Op B, int k0, char* sm, int tid) {
    hf* Ah = (hf*)sm;
    hf* Bh = (hf*)(sm + MAT_B);
    #pragma unroll
    for (int i = 0; i < 2; ++i) {
        int idx = tid + 256*i;
        if (!TA) {
            int row = idx >> 2, ch = idx & 3;
            cpa16(Ah + row*NT_STRIDE + ch*8, A.p + (size_t)row*A.ld + k0 + ch*8);
        } else {
            int row = idx >> 4, ch = idx & 15;
            cpa16(Ah + row*T_STRIDE + ch*8, A.p + (size_t)(k0 + row)*A.ld + ch*8);
        }
        if (!TB) {
            int row = idx >> 2, ch = idx & 3;
            cpa16(Bh + row*NT_STRIDE + ch*8, B.p + (size_t)row*B.ld + k0 + ch*8);
        } else {
            int row = idx >> 4, ch = idx & 15;
            cpa16(Bh + row*T_STRIDE + ch*8, B.p + (size_t)(k0 + row)*B.ld + ch*8);
        }
    }
}

struct LaneOff {
    uint32_t a[2];
    uint32_t b[4];
};
template<int TA, int TB>
__device__ __forceinline__ LaneOff make_off(int lane, int wm, int wn) {
    LaneOff lo;
    #pragma unroll
    for (int mt = 0; mt < 2; ++mt) {
        lo.a[mt] = (!TA)
            ? (uint32_t)(((wm + mt*16 + (lane & 15))*NT_STRIDE + ((lane >> 4) << 3)) * 2)
            : (uint32_t)(((((lane >> 4) << 3) + (lane & 7))*T_STRIDE + wm + mt*16 + (lane & 8)) * 2);
    }
    #pragma unroll
    for (int nq = 0; nq < 4; ++nq) {
        lo.b[nq] = (!TB)
            ? (uint32_t)(MAT_B + ((wn + nq*16 + (lane & 15))*NT_STRIDE + ((lane >> 4) << 3)) * 2)
            : (uint32_t)(MAT_B + (((lane & 15))*T_STRIDE + wn + nq*16 + ((lane >> 4) << 3)) * 2);
    }
    return lo;
}

template<int TA, int TB>
__device__ __forceinline__ void compute16(uint32_t smaddr, int ks, const LaneOff& lo,
                                          float acc[2][8][4]) {
    const uint32_t dA = (!TA) ? (uint32_t)(2*ks) : (uint32_t)(2*ks*T_STRIDE);
    const uint32_t dB = (!TB) ? (uint32_t)(2*ks) : (uint32_t)(2*ks*T_STRIDE);
    uint32_t ah[2][4], bh[8][2];
    #pragma unroll
    for (int mt = 0; mt < 2; ++mt) {
        uint32_t a = smaddr + lo.a[mt] + dA;
        if (!TA) ldsm4a(ah[mt], a); else ldsm4ta(ah[mt], a);
    }
    #pragma unroll
    for (int nq = 0; nq < 4; ++nq) {
        uint32_t a = smaddr + lo.b[nq] + dB;
        uint32_t r[4];
        if (!TB) {
            ldsm4a(r, a);
            bh[2*nq][0]=r[0]; bh[2*nq][1]=r[2]; bh[2*nq+1][0]=r[1]; bh[2*nq+1][1]=r[3];
        } else {
            ldsm4ta(r, a);
            bh[2*nq][0]=r[0]; bh[2*nq][1]=r[1]; bh[2*nq+1][0]=r[2]; bh[2*nq+1][1]=r[3];
        }
    }
    #pragma unroll
    for (int mt = 0; mt < 2; ++mt)
        #pragma unroll
        for (int nt = 0; nt < 8; ++nt)
            mma_f16(acc[mt][nt], ah[mt], bh[nt]);
}

// 3-stage pipeline: prefetch 2 tiles ahead, one __syncthreads per k-iter.
template<int TA, int TB>
__device__ __forceinline__ void gemm_core(Op A, Op B, int K, float acc[2][8][4],
                                          char* smbase, int tid) {
    const int lane = tid & 31, wid = tid >> 5;
    const int wm = (wid & 3) * 32, wn = (wid >> 2) * 64;
    const LaneOff lo = make_off<TA,TB>(lane, wm, wn);
    const uint32_t base0 = (uint32_t)__cvta_generic_to_shared(smbase);
    const int KT = K >> 5;   // >= 4 always
    stage<TA,TB>(A, B, 0, smbase, tid);            cp_commit();
    stage<TA,TB>(A, B, 32, smbase + STAGE_B, tid); cp_commit();
    int buf = 0;
    for (int kt = 0; kt < KT; ++kt) {
        if (kt + 1 < KT) cp_wait1(); else cp_wait0();
        __syncthreads();
        uint32_t cur = base0 + (uint32_t)(buf*STAGE_B);
        compute16<TA,TB>(cur, 0,  lo, acc);
        compute16<TA,TB>(cur, 16, lo, acc);
        if (kt + 2 < KT) {
            int nb = buf + 2; if (nb >= 3) nb -= 3;
            stage<TA,TB>(A, B, (kt+2) << 5, smbase + nb*STAGE_B, tid);
            cp_commit();
        }
        buf = (buf + 1 == 3) ? 0 : buf + 1;
    }
    __syncthreads();
}

#define GEMM_SMEM extern __shared__ char sm_[];

#define EPI_COORDS \
    const int lane = tid & 31, wid = tid >> 5; \
    const int gid = lane >> 2, tig = lane & 3; \
    const int wm = (wid & 3) * 32, wn = (wid >> 2) * 64;

#define EPI_LOOP(BODY) \
    _Pragma("unroll") for (int mt = 0; mt < 2; ++mt) \
    _Pragma("unroll") for (int nt = 0; nt < 8; ++nt) \
    _Pragma("unroll") for (int ci = 0; ci < 4; ++ci) { \
        int mr = wm + mt*16 + gid + ((ci >> 1) ? 8 : 0); \
        int nr = wn + nt*8 + tig*2 + (ci & 1); \
        float v = acc[mt][nt][ci]; \
        BODY \
    }

// ---------------- GEMM kernels ----------------
__global__ void __launch_bounds__(256, 2) tc_proj3() {
    GEMM_SMEM;
    int tid = threadIdx.x;
    int m0 = blockIdx.y * 128, n0 = blockIdx.x * 128;
    int which = blockIdx.z;
    const hf* wh = (which==0) ? d_wqh : (which==1) ? d_wkh : d_wvh;
    float acc[2][8][4] = {};
    Op A{d_hsh + (size_t)m0*DD, DD};
    Op B{wh + (size_t)n0*DD, DD};
    gemm_core<0,0>(A, B, DD, acc, sm_, tid);
    EPI_COORDS;
    if (which == 0) {
        EPI_LOOP({
            size_t o = (size_t)(m0+mr)*DD + n0 + nr;
            v = (v > 0.f) ? v + 1.f : expf(v);
            d_sqh[o] = __float2half_rn(v);
        })
    } else if (which == 1) {
        EPI_LOOP({
            size_t o = (size_t)(m0+mr)*DD + n0 + nr;
            v = (v > 0.f) ? v + 1.f : expf(v);
            d_skh[o] = __float2half_rn(v);
        })
    } else {
        EPI_LOOP({
            size_t o = (size_t)(m0+mr)*DD + n0 + nr;
            d_vh[o] = __float2half_rn(v);
        })
    }
}

// fused wave2: memout 256 | kv 2048 | scores 32
__global__ void __launch_bounds__(256, 2) wave2() {
    GEMM_SMEM;
    int tid = threadIdx.x;
    int bid = blockIdx.x;
    if (bid < 256) {
        int m0 = (bid >> 3) * 128, n0 = (bid & 7) * 128;
        float acc[2][8][4] = {};
        Op A{d_sqh + (size_t)m0*DD, DD};
        Op B{d_memTh + (size_t)n0*DD, DD};
        gemm_core<0,0>(A, B, DD, acc, sm_, tid);
        float gs = d_scal[0] * d_scal[1];
        EPI_COORDS;
        EPI_LOOP({
            d_memout[(size_t)(m0+mr)*DD + n0 + nr] = v * gs / d_normq[m0+mr];
        })
    } else if (bid < 2304) {
        int idx = bid - 256;
        int bn = idx >> 6, loc = idx & 63;
        int b = bn >> 4, n = bn & 15;
        size_t cb = (size_t)(b*SEQ + n*CH)*DD;
        int m0 = (loc >> 3) * 128, n0 = (loc & 7) * 128;
        float acc[2][8][4] = {};
        Op A{d_skh + cb + m0, DD};
        Op B{d_vh + cb + n0, DD};
        gemm_core<1,1>(A, B, CH, acc, sm_, tid);
        hf* C = d_Gh + (size_t)bn*DD*DD;
        EPI_COORDS;
        EPI_LOOP({
            C[(size_t)(m0+mr)*DD + n0 + nr] = __float2half_rn(v);
        })
    } else {
        int bn = bid - 2304;
        int b = bn >> 4, n = bn & 15;
        size_t cb = (size_t)(b*SEQ + n*CH)*DD;
        float acc[2][8][4] = {};
        Op A{d_sqh + cb, DD};
        Op B{d_skh + cb, DD};
        gemm_core<0,0>(A, B, DD, acc, sm_, tid);
        size_t co = (size_t)bn*CH*CH;
        EPI_COORDS;
        EPI_LOOP({
            float m = (nr <= mr) ? v : 0.f;
            d_Abh[co + (size_t)mr*CH + nr] = __float2half_rn(m);
        })
    }
}

// fused wave3: gprefix (8192 blocks) + den (512 blocks, fp16 Abh)
__global__ void __launch_bounds__(256) wave3() {
    int bid = blockIdx.x, tid = threadIdx.x;
    if (bid < 8192) {
        size_t idx = (size_t)bid*256 + tid;
        int b = (int)(idx / ((size_t)DD*DD));
        size_t rem = idx % ((size_t)DD*DD);
        float run = 0.f;
        for (int n = 0; n < NCH; ++n) {
            size_t off = ((size_t)(b*NCH + n)*DD*DD) + rem;
            float t = __half2float(d_Gh[off]);
            d_Sph[off] = __float2half_rn(run);
            run += t;
        }
    } else {
        int warp = ((bid - 8192)*256 + tid) >> 5;
        int lane = tid & 31;
        if (warp >= BSZ*NCH*CH) return;
        int bn = warp / CH, i = warp % CH;
        int b = bn >> 4, n = bn & 15;
        const hf* qr = d_sqh + (size_t)(b*SEQ + n*CH + i)*DD;
        const float* zr = d_zz + (size_t)bn*DD;
        float s = 0.f;
        for (int k = lane; k < DD; k += 32) s += __half2float(qr[k]) * zr[k];
        const hf* ar = d_Abh + (size_t)bn*CH*CH + (size_t)i*CH;
        for (int j = lane; j < CH; j += 32) s += __half2float(ar[j]);
        #pragma unroll
        for (int o = 16; o > 0; o >>= 1) s += __shfl_xor_sync(0xffffffffu, s, o);
        if (lane == 0) d_den[warp] = fmaxf(s, EPSV);
    }
}

// attn: local = (sq @ Sp + Abuf @ v)/den; epilogue fuses combine -> d_cmh
__global__ void __launch_bounds__(256, 2) tc_attn() {
    GEMM_SMEM;
    int tid = threadIdx.x;
    int bn = blockIdx.z; int b = bn >> 4, n = bn & 15;
    size_t cb = (size_t)(b*SEQ + n*CH)*DD;
    int n0 = blockIdx.x * 128;
    float acc[2][8][4] = {};
    {
        Op A{d_sqh + cb, DD};
        Op B{d_Sph + (size_t)bn*DD*DD + n0, DD};   // trans [d][e]
        gemm_core<0,1>(A, B, DD, acc, sm_, tid);
    }
    {
        Op A{d_Abh + (size_t)bn*CH*CH, CH};
        Op B{d_vh + cb + n0, DD};                  // trans [c][e]
        gemm_core<0,1>(A, B, CH, acc, sm_, tid);
    }
    float og = 1.f - d_scal[0];
    EPI_COORDS;
    EPI_LOOP({
        size_t o = cb + (size_t)mr*DD + n0 + nr;
        float cm = d_memout[o] + og * v / d_den[bn*CH + mr];
        d_cmh[o] = __float2half_rn(cm);
    })
}

__global__ void __launch_bounds__(256, 2) tc_final(float* __restrict__ Out) {
    GEMM_SMEM;
    int tid = threadIdx.x;
    int m0 = blockIdx.y * 128, n0 = blockIdx.x * 128;
    float acc[2][8][4] = {};
    Op A{d_cmh + (size_t)m0*DD, DD};
    Op B{d_woh + (size_t)n0*DD, DD};
    gemm_core<0,0>(A, B, DD, acc, sm_, tid);
    EPI_COORDS;
    EPI_LOOP({
        Out[(size_t)(m0+mr)*DD + n0 + nr] = v;
    })
}

// ---------------- launcher ----------------
extern "C" void kernel_launch(void* const* d_in, const int* in_sizes, int n_in,
                              void* d_out, int out_size) {
    const float* hs    = (const float*)d_in[0];
    const float* wq    = (const float*)d_in[1];
    const float* wk    = (const float*)d_in[2];
    const float* wv    = (const float*)d_in[3];
    const float* wo    = (const float*)d_in[4];
    const float* gate  = (const float*)d_in[5];
    const float* mem   = (const float*)d_in[6];
    const float* mnorm = (const float*)d_in[7];
    float* out = (float*)d_out;

    cudaFuncSetAttribute(tc_proj3, cudaFuncAttributeMaxDynamicSharedMemorySize, SMEM_TOT);
    cudaFuncSetAttribute(wave2,    cudaFuncAttributeMaxDynamicSharedMemorySize, SMEM_TOT);
    cudaFuncSetAttribute(tc_attn,  cudaFuncAttributeMaxDynamicSharedMemorySize, SMEM_TOT);
    cudaFuncSetAttribute(tc_final, cudaFuncAttributeMaxDynamicSharedMemorySize, SMEM_TOT);

    scalars_kernel<<<1, 1024>>>(gate, mnorm);

    cvt_all<<<12288, 256>>>((const float4*)hs, (const float4*)wq, (const float4*)wk,
                            (const float4*)wv, (const float4*)wo, mem);

    dim3 gP(DD/128, MTOT/128, 3);       // (8, 32, 3)
    tc_proj3<<<gP, 256, SMEM_TOT>>>();

    normq_kernel<<<(MTOT*32 + 255)/256, 256>>>(mnorm);
    zc_kernel<<<(BSZ*NCH*DD + 255)/256, 256>>>();
    zprefix_kernel<<<(BSZ*DD + 255)/256, 256>>>();

    wave2<<<2336, 256, SMEM_TOT>>>();
    wave3<<<8704, 256>>>();

    dim3 gAt(DD/128, 1, BSZ*NCH);       // (8, 1, 32)
    tc_attn<<<gAt, 256, SMEM_TOT>>>();

    dim3 gM(DD/128, MTOT/128);          // (8, 32)
    tc_final<<<gM, 256, SMEM_TOT>>>(out);
}

// round 15
// speedup vs baseline: 1.2409x; 1.0057x over previous
#include <cuda_runtime.h>
#include <cuda_fp16.h>
#include <math.h>
#include <stdint.h>

#define BSZ 2
#define SEQ 2048
#define DD 1024
#define CH 128
#define NCH 16
#define MTOT (BSZ*SEQ)        // 4096
#define EPSV 1e-6f

typedef __half hf;

// ---------------- scratch ----------------
__device__ float d_memout[MTOT*DD];              // g*act*memout/normq
__device__ float d_zz[BSZ*NCH*DD];
__device__ float d_den[BSZ*NCH*CH];
__device__ float d_normq[MTOT];
__device__ float d_scal[2];

// fp16 operand buffers
__device__ hf d_hsh[MTOT*DD];
__device__ hf d_wqh[DD*DD];
__device__ hf d_wkh[DD*DD];
__device__ hf d_wvh[DD*DD];
__device__ hf d_woh[DD*DD];
__device__ hf d_memTh[DD*DD];
__device__ hf d_sqh[MTOT*DD];
__device__ hf d_skh[MTOT*DD];
__device__ hf d_vh [MTOT*DD];
__device__ hf d_Gh [(size_t)BSZ*NCH*DD*DD];      // per-chunk KV products
__device__ hf d_Sph[(size_t)BSZ*NCH*DD*DD];      // exclusive prefix of G
__device__ hf d_Abh[BSZ*NCH*CH*CH];
__device__ hf d_cmh[MTOT*DD];

// ---------------- small kernels ----------------
__global__ void scalars_kernel(const float* __restrict__ gate,
                               const float* __restrict__ mnorm) {
    __shared__ float sh[1024];
    int t = threadIdx.x;
    sh[t] = mnorm[t];
    __syncthreads();
    for (int s = 512; s > 0; s >>= 1) { if (t < s) sh[t] += sh[t+s]; __syncthreads(); }
    if (t == 0) {
        d_scal[0] = 1.f / (1.f + expf(-gate[0]));
        d_scal[1] = (sh[0] >= EPSV) ? 1.f : 0.f;
    }
}

__device__ __forceinline__ void cvt4hi(const float4* src, uint2* hi, int i) {
    float4 x = src[i];
    union { __half2 b[2]; uint2 u; } uh;
    uh.b[0] = __halves2half2(__float2half_rn(x.x), __float2half_rn(x.y));
    uh.b[1] = __halves2half2(__float2half_rn(x.z), __float2half_rn(x.w));
    hi[i] = uh.u;
}

// fused converts: hs | wq | wk | wv | wo | memT
__global__ void cvt_all(const float4* __restrict__ hs,
                        const float4* __restrict__ wq, const float4* __restrict__ wk,
                        const float4* __restrict__ wv, const float4* __restrict__ wo,
                        const float* __restrict__ mem) {
    int bid = blockIdx.x, tid = threadIdx.x;
    if (bid < 4096)        cvt4hi(hs, (uint2*)d_hsh, bid*256 + tid);
    else if (bid < 5120)   cvt4hi(wq, (uint2*)d_wqh, (bid-4096)*256 + tid);
    else if (bid < 6144)   cvt4hi(wk, (uint2*)d_wkh, (bid-5120)*256 + tid);
    else if (bid < 7168)   cvt4hi(wv, (uint2*)d_wvh, (bid-6144)*256 + tid);
    else if (bid < 8192)   cvt4hi(wo, (uint2*)d_woh, (bid-7168)*256 + tid);
    else {
        int idx = (bid-8192)*256 + tid;           // DD*DD
        int k = idx & (DD-1), n = idx >> 10;
        d_memTh[(size_t)n*DD + k] = __float2half_rn(mem[(size_t)k*DD + n]);
    }
}

__global__ void normq_kernel(const float* __restrict__ mnorm) {
    int warp = (blockIdx.x * blockDim.x + threadIdx.x) >> 5;
    int lane = threadIdx.x & 31;
    if (warp >= MTOT) return;
    const hf* row = d_sqh + (size_t)warp * DD;
    float s = 0.f;
    for (int k = lane; k < DD; k += 32) s += __half2float(row[k]) * mnorm[k];
    #pragma unroll
    for (int o = 16; o > 0; o >>= 1) s += __shfl_xor_sync(0xffffffffu, s, o);
    if (lane == 0) d_normq[warp] = fmaxf(s, EPSV);
}

__global__ void zc_kernel() {
    int idx = blockIdx.x * blockDim.x + threadIdx.x;
    if (idx >= BSZ*NCH*DD) return;
    int d = idx % DD; int bn = idx / DD;
    int b = bn >> 4, n = bn & 15;
    const hf* base = d_skh + (size_t)(b*SEQ + n*CH)*DD + d;
    float s = 0.f;
    #pragma unroll 4
    for (int i = 0; i < CH; ++i) s += __half2float(base[(size_t)i*DD]);
    d_zz[idx] = s;
}

__global__ void zprefix_kernel() {
    int idx = blockIdx.x * blockDim.x + threadIdx.x;
    if (idx >= BSZ*DD) return;
    int b = idx / DD, d = idx % DD;
    float run = 0.f;
    for (int n = 0; n < NCH; ++n) {
        float* p = d_zz + (size_t)(b*NCH + n)*DD + d;
        float t = *p; *p = run; run += t;
    }
}

// ---------------- tensor-core GEMM core (pure fp16, K-step 32, 3-stage) ----------------
#define NT_STRIDE 40
#define T_STRIDE 136
#define MAT_B 10240
#define STAGE_B (2*MAT_B)     // 20480
#define SMEM_PIPE (3*STAGE_B) // 61440

// one-shot (K=128) layout: both matrices 128 rows x 136 halfs
#define OS_STRIDE 136
#define OS_MAT_B (128*OS_STRIDE*2)   // 34816
#define SMEM_OS (2*OS_MAT_B)         // 69632

__device__ __forceinline__ void cpa16(void* dst, const void* src) {
    uint32_t d = (uint32_t)__cvta_generic_to_shared(dst);
    asm volatile("cp.async.cg.shared.global [%0], [%1], 16;" :: "r"(d), "l"(src));
}
__device__ __forceinline__ void cp_commit() { asm volatile("cp.async.commit_group;"); }
__device__ __forceinline__ void cp_wait1()  { asm volatile("cp.async.wait_group 1;"); }
__device__ __forceinline__ void cp_wait0()  { asm volatile("cp.async.wait_group 0;"); }

__device__ __forceinline__ void ldsm4a(uint32_t* r, uint32_t a) {
    asm volatile("ldmatrix.sync.aligned.m8n8.x4.shared.b16 {%0,%1,%2,%3}, [%4];"
        : "=r"(r[0]), "=r"(r[1]), "=r"(r[2]), "=r"(r[3]) : "r"(a));
}
__device__ __forceinline__ void ldsm4ta(uint32_t* r, uint32_t a) {
    asm volatile("ldmatrix.sync.aligned.m8n8.x4.trans.shared.b16 {%0,%1,%2,%3}, [%4];"
        : "=r"(r[0]), "=r"(r[1]), "=r"(r[2]), "=r"(r[3]) : "r"(a));
}
__device__ __forceinline__ void mma_f16(float* c, const uint32_t* a, const uint32_t* b) {
    asm volatile("mma.sync.aligned.m16n8k16.row.col.f32.f16.f16.f32 "
        "{%0,%1,%2,%3}, {%4,%5,%6,%7}, {%8,%9}, {%0,%1,%2,%3};"
        : "+f"(c[0]), "+f"(c[1]), "+f"(c[2]), "+f"(c[3])
        : "r"(a[0]), "r"(a[1]), "r"(a[2]), "r"(a[3]), "r"(b[0]), "r"(b[1]));
}

struct Op { const hf* p; int ld; };

template<int TA, int TB>
__device__ __forceinline__ void stage(Op A, Op B, int k0, char* sm, int tid) {
    hf* Ah = (hf*)sm;
    hf* Bh = (hf*)(sm + MAT_B);
    #pragma unroll
    for (int i = 0; i < 2; ++i) {
        int idx = tid + 256*i;
        if (!TA) {
            int row = idx >> 2, ch = idx & 3;
            cpa16(Ah + row*NT_STRIDE + ch*8, A.p + (size_t)row*A.ld + k0 + ch*8);
        } else {
            int row = idx >> 4, ch = idx & 15;
            cpa16(Ah + row*T_STRIDE + ch*8, A.p + (size_t)(k0 + row)*A.ld + ch*8);
        }
        if (!TB) {
            int row = idx >> 2, ch = idx & 3;
            cpa16(Bh + row*NT_STRIDE + ch*8, B.p + (size_t)row*B.ld + k0 + ch*8);
        } else {
            int row = idx >> 4, ch = idx & 15;
            cpa16(Bh + row*T_STRIDE + ch*8, B.p + (size_t)(k0 + row)*B.ld + ch*8);
        }
    }
}

struct LaneOff {
    uint32_t a[2];
    uint32_t b[4];
};
template<int TA, int TB>
__device__ __forceinline__ LaneOff make_off(int lane, int wm, int wn) {
    LaneOff lo;
    #pragma unroll
    for (int mt = 0; mt < 2; ++mt) {
        lo.a[mt] = (!TA)
            ? (uint32_t)(((wm + mt*16 + (lane & 15))*NT_STRIDE + ((lane >> 4) << 3)) * 2)
            : (uint32_t)(((((lane >> 4) << 3) + (lane & 7))*T_STRIDE + wm + mt*16 + (lane & 8)) * 2);
    }
    #pragma unroll
    for (int nq = 0; nq < 4; ++nq) {
        lo.b[nq] = (!TB)
            ? (uint32_t)(MAT_B + ((wn + nq*16 + (lane & 15))*NT_STRIDE + ((lane >> 4) << 3)) * 2)
            : (uint32_t)(MAT_B + (((lane & 15))*T_STRIDE + wn + nq*16 + ((lane >> 4) << 3)) * 2);
    }
    return lo;
}

template<int TA, int TB>
__device__ __forceinline__ void compute16(uint32_t smaddr, int ks, const LaneOff& lo,
                                          float acc[2][8][4]) {
    const uint32_t dA = (!TA) ? (uint32_t)(2*ks) : (uint32_t)(2*ks*T_STRIDE);
    const uint32_t dB = (!TB) ? (uint32_t)(2*ks) : (uint32_t)(2*ks*T_STRIDE);
    uint32_t ah[2][4], bh[8][2];
    #pragma unroll
    for (int mt = 0; mt < 2; ++mt) {
        uint32_t a = smaddr + lo.a[mt] + dA;
        if (!TA) ldsm4a(ah[mt], a); else ldsm4ta(ah[mt], a);
    }
    #pragma unroll
    for (int nq = 0; nq < 4; ++nq) {
        uint32_t a = smaddr + lo.b[nq] + dB;
        uint32_t r[4];
        if (!TB) {
            ldsm4a(r, a);
            bh[2*nq][0]=r[0]; bh[2*nq][1]=r[2]; bh[2*nq+1][0]=r[1]; bh[2*nq+1][1]=r[3];
        } else {
            ldsm4ta(r, a);
            bh[2*nq][0]=r[0]; bh[2*nq][1]=r[1]; bh[2*nq+1][0]=r[2]; bh[2*nq+1][1]=r[3];
        }
    }
    #pragma unroll
    for (int mt = 0; mt < 2; ++mt)
        #pragma unroll
        for (int nt = 0; nt < 8; ++nt)
            mma_f16(acc[mt][nt], ah[mt], bh[nt]);
}

// 3-stage pipeline (K multiple of 32, KT>=4): one __syncthreads per k-iter.
template<int TA, int TB>
__device__ __forceinline__ void gemm_core(Op A, Op B, int K, float acc[2][8][4],
                                          char* smbase, int tid) {
    const int lane = tid & 31, wid = tid >> 5;
    const int wm = (wid & 3) * 32, wn = (wid >> 2) * 64;
    const LaneOff lo = make_off<TA,TB>(lane, wm, wn);
    const uint32_t base0 = (uint32_t)__cvta_generic_to_shared(smbase);
    const int KT = K >> 5;
    stage<TA,TB>(A, B, 0, smbase, tid);            cp_commit();
    stage<TA,TB>(A, B, 32, smbase + STAGE_B, tid); cp_commit();
    int buf = 0;
    for (int kt = 0; kt < KT; ++kt) {
        if (kt + 1 < KT) cp_wait1(); else cp_wait0();
        __syncthreads();
        uint32_t cur = base0 + (uint32_t)(buf*STAGE_B);
        compute16<TA,TB>(cur, 0,  lo, acc);
        compute16<TA,TB>(cur, 16, lo, acc);
        if (kt + 2 < KT) {
            int nb = buf + 2; if (nb >= 3) nb -= 3;
            stage<TA,TB>(A, B, (kt+2) << 5, smbase + nb*STAGE_B, tid);
            cp_commit();
        }
        buf = (buf + 1 == 3) ? 0 : buf + 1;
    }
    __syncthreads();
}

// ---- one-shot K=128 path: full tiles staged once, 1 sync, 8 mma bursts ----
template<int TA, int TB>
__device__ __forceinline__ void compute16o(uint32_t smaddr, int ks, int lane,
                                           int wm, int wn, float acc[2][8][4]) {
    uint32_t ah[2][4], bh[8][2];
    #pragma unroll
    for (int mt = 0; mt < 2; ++mt) {
        uint32_t a;
        if (!TA) {
            a = smaddr + (uint32_t)(((wm + mt*16 + (lane & 15))*OS_STRIDE + ks + ((lane >> 4) << 3)) * 2);
            ldsm4a(ah[mt], a);
        } else {
            a = smaddr + (uint32_t)(((ks + ((lane >> 4) << 3) + (lane & 7))*OS_STRIDE + wm + mt*16 + (lane & 8)) * 2);
            ldsm4ta(ah[mt], a);
        }
    }
    #pragma unroll
    for (int nq = 0; nq < 4; ++nq) {
        uint32_t a;
        uint32_t r[4];
        if (!TB) {
            a = smaddr + (uint32_t)(OS_MAT_B + ((wn + nq*16 + (lane & 15))*OS_STRIDE + ks + ((lane >> 4) << 3)) * 2);
            ldsm4a(r, a);
            bh[2*nq][0]=r[0]; bh[2*nq][1]=r[2]; bh[2*nq+1][0]=r[1]; bh[2*nq+1][1]=r[3];
        } else {
            a = smaddr + (uint32_t)(OS_MAT_B + ((ks + (lane & 15))*OS_STRIDE + wn + nq*16 + ((lane >> 4) << 3)) * 2);
            ldsm4ta(r, a);
            bh[2*nq][0]=r[0]; bh[2*nq][1]=r[1]; bh[2*nq+1][0]=r[2]; bh[2*nq+1][1]=r[3];
        }
    }
    #pragma unroll
    for (int mt = 0; mt < 2; ++mt)
        #pragma unroll
        for (int nt = 0; nt < 8; ++nt)
            mma_f16(acc[mt][nt], ah[mt], bh[nt]);
}

// K=128 one-shot. Staging identical for NT/T (row-major 128x128 copy);
// interpretation handled in compute16o.
template<int TA, int TB>
__device__ __forceinline__ void gemm_once(Op A, Op B, float acc[2][8][4],
                                          char* smbase, int tid) {
    hf* Ah = (hf*)smbase;
    hf* Bh = (hf*)(smbase + OS_MAT_B);
    #pragma unroll
    for (int i = 0; i < 8; ++i) {
        int idx = tid + 256*i;           // 2048 chunks per matrix
        int row = idx >> 4, ch = idx & 15;
        cpa16(Ah + row*OS_STRIDE + ch*8, A.p + (size_t)row*A.ld + ch*8);
        cpa16(Bh + row*OS_STRIDE + ch*8, B.p + (size_t)row*B.ld + ch*8);
    }
    cp_commit();
    cp_wait0();
    __syncthreads();
    const int lane = tid & 31, wid = tid >> 5;
    const int wm = (wid & 3) * 32, wn = (wid >> 2) * 64;
    const uint32_t base = (uint32_t)__cvta_generic_to_shared(smbase);
    #pragma unroll
    for (int ks = 0; ks < 128; ks += 16)
        compute16o<TA,TB>(base, ks, lane, wm, wn, acc);
    __syncthreads();
}

#define GEMM_SMEM extern __shared__ char sm_[];

#define EPI_COORDS \
    const int lane = tid & 31, wid = tid >> 5; \
    const int gid = lane >> 2, tig = lane & 3; \
    const int wm = (wid & 3) * 32, wn = (wid >> 2) * 64;

#define EPI_LOOP(BODY) \
    _Pragma("unroll") for (int mt = 0; mt < 2; ++mt) \
    _Pragma("unroll") for (int nt = 0; nt < 8; ++nt) \
    _Pragma("unroll") for (int ci = 0; ci < 4; ++ci) { \
        int mr = wm + mt*16 + gid + ((ci >> 1) ? 8 : 0); \
        int nr = wn + nt*8 + tig*2 + (ci & 1); \
        float v = acc[mt][nt][ci]; \
        BODY \
    }

// ---------------- GEMM kernels ----------------
__global__ void __launch_bounds__(256, 2) tc_proj3() {
    GEMM_SMEM;
    int tid = threadIdx.x;
    int m0 = blockIdx.y * 128, n0 = blockIdx.x * 128;
    int which = blockIdx.z;
    const hf* wh = (which==0) ? d_wqh : (which==1) ? d_wkh : d_wvh;
    float acc[2][8][4] = {};
    Op A{d_hsh + (size_t)m0*DD, DD};
    Op B{wh + (size_t)n0*DD, DD};
    gemm_core<0,0>(A, B, DD, acc, sm_, tid);
    EPI_COORDS;
    if (which == 0) {
        EPI_LOOP({
            size_t o = (size_t)(m0+mr)*DD + n0 + nr;
            v = (v > 0.f) ? v + 1.f : expf(v);
            d_sqh[o] = __float2half_rn(v);
        })
    } else if (which == 1) {
        EPI_LOOP({
            size_t o = (size_t)(m0+mr)*DD + n0 + nr;
            v = (v > 0.f) ? v + 1.f : expf(v);
            d_skh[o] = __float2half_rn(v);
        })
    } else {
        EPI_LOOP({
            size_t o = (size_t)(m0+mr)*DD + n0 + nr;
            d_vh[o] = __float2half_rn(v);
        })
    }
}

// fused wave2: memout 256 | kv 2048 (one-shot) | scores 32
__global__ void __launch_bounds__(256, 2) wave2() {
    GEMM_SMEM;
    int tid = threadIdx.x;
    int bid = blockIdx.x;
    if (bid < 2048) {
        // kv first (majority): G[bn][d][e] = sum_c sk[c][d] * v[c][e], one-shot K=128
        int bn = bid >> 6, loc = bid & 63;
        int b = bn >> 4, n = bn & 15;
        size_t cb = (size_t)(b*SEQ + n*CH)*DD;
        int m0 = (loc >> 3) * 128, n0 = (loc & 7) * 128;
        float acc[2][8][4] = {};
        Op A{d_skh + cb + m0, DD};
        Op B{d_vh + cb + n0, DD};
        gemm_once<1,1>(A, B, acc, sm_, tid);
        hf* C = d_Gh + (size_t)bn*DD*DD;
        EPI_COORDS;
        EPI_LOOP({
            C[(size_t)(m0+mr)*DD + n0 + nr] = __float2half_rn(v);
        })
    } else if (bid < 2304) {
        int idx = bid - 2048;
        int m0 = (idx >> 3) * 128, n0 = (idx & 7) * 128;
        float acc[2][8][4] = {};
        Op A{d_sqh + (size_t)m0*DD, DD};
        Op B{d_memTh + (size_t)n0*DD, DD};
        gemm_core<0,0>(A, B, DD, acc, sm_, tid);
        float gs = d_scal[0] * d_scal[1];
        EPI_COORDS;
        EPI_LOOP({
            d_memout[(size_t)(m0+mr)*DD + n0 + nr] = v * gs / d_normq[m0+mr];
        })
    } else {
        int bn = bid - 2304;
        int b = bn >> 4, n = bn & 15;
        size_t cb = (size_t)(b*SEQ + n*CH)*DD;
        float acc[2][8][4] = {};
        Op A{d_sqh + cb, DD};
        Op B{d_skh + cb, DD};
        gemm_core<0,0>(A, B, DD, acc, sm_, tid);
        size_t co = (size_t)bn*CH*CH;
        EPI_COORDS;
        EPI_LOOP({
            float m = (nr <= mr) ? v : 0.f;
            d_Abh[co + (size_t)mr*CH + nr] = __float2half_rn(m);
        })
    }
}

// fused wave3: gprefix (8192 blocks) + den (512 blocks, fp16 Abh)
__global__ void __launch_bounds__(256) wave3() {
    int bid = blockIdx.x, tid = threadIdx.x;
    if (bid < 8192) {
        size_t idx = (size_t)bid*256 + tid;
        int b = (int)(idx / ((size_t)DD*DD));
        size_t rem = idx % ((size_t)DD*DD);
        float run = 0.f;
        for (int n = 0; n < NCH; ++n) {
            size_t off = ((size_t)(b*NCH + n)*DD*DD) + rem;
            float t = __half2float(d_Gh[off]);
            d_Sph[off] = __float2half_rn(run);
            run += t;
        }
    } else {
        int warp = ((bid - 8192)*256 + tid) >> 5;
        int lane = tid & 31;
        if (warp >= BSZ*NCH*CH) return;
        int bn = warp / CH, i = warp % CH;
        int b = bn >> 4, n = bn & 15;
        const hf* qr = d_sqh + (size_t)(b*SEQ + n*CH + i)*DD;
        const float* zr = d_zz + (size_t)bn*DD;
        float s = 0.f;
        for (int k = lane; k < DD; k += 32) s += __half2float(qr[k]) * zr[k];
        const hf* ar = d_Abh + (size_t)bn*CH*CH + (size_t)i*CH;
        for (int j = lane; j < CH; j += 32) s += __half2float(ar[j]);
        #pragma unroll
        for (int o = 16; o > 0; o >>= 1) s += __shfl_xor_sync(0xffffffffu, s, o);
        if (lane == 0) d_den[warp] = fmaxf(s, EPSV);
    }
}

// attn: local = (sq @ Sp + Abuf @ v)/den; phase2 one-shot; combine fused -> d_cmh
__global__ void __launch_bounds__(256, 2) tc_attn() {
    GEMM_SMEM;
    int tid = threadIdx.x;
    int bn = blockIdx.z; int b = bn >> 4, n = bn & 15;
    size_t cb = (size_t)(b*SEQ + n*CH)*DD;
    int n0 = blockIdx.x * 128;
    float acc[2][8][4] = {};
    {
        Op A{d_sqh + cb, DD};
        Op B{d_Sph + (size_t)bn*DD*DD + n0, DD};   // trans [d][e]
        gemm_core<0,1>(A, B, DD, acc, sm_, tid);
    }
    {
        Op A{d_Abh + (size_t)bn*CH*CH, CH};
        Op B{d_vh + cb + n0, DD};                  // trans [c][e]
        gemm_once<0,1>(A, B, acc, sm_, tid);
    }
    float og = 1.f - d_scal[0];
    EPI_COORDS;
    EPI_LOOP({
        size_t o = cb + (size_t)mr*DD + n0 + nr;
        float cm = d_memout[o] + og * v / d_den[bn*CH + mr];
        d_cmh[o] = __float2half_rn(cm);
    })
}

__global__ void __launch_bounds__(256, 2) tc_final(float* __restrict__ Out) {
    GEMM_SMEM;
    int tid = threadIdx.x;
    int m0 = blockIdx.y * 128, n0 = blockIdx.x * 128;
    float acc[2][8][4] = {};
    Op A{d_cmh + (size_t)m0*DD, DD};
    Op B{d_woh + (size_t)n0*DD, DD};
    gemm_core<0,0>(A, B, DD, acc, sm_, tid);
    EPI_COORDS;
    EPI_LOOP({
        Out[(size_t)(m0+mr)*DD + n0 + nr] = v;
    })
}

// ---------------- launcher ----------------
extern "C" void kernel_launch(void* const* d_in, const int* in_sizes, int n_in,
                              void* d_out, int out_size) {
    const float* hs    = (const float*)d_in[0];
    const float* wq    = (const float*)d_in[1];
    const float* wk    = (const float*)d_in[2];
    const float* wv    = (const float*)d_in[3];
    const float* wo    = (const float*)d_in[4];
    const float* gate  = (const float*)d_in[5];
    const float* mem   = (const float*)d_in[6];
    const float* mnorm = (const float*)d_in[7];
    float* out = (float*)d_out;

    cudaFuncSetAttribute(tc_proj3, cudaFuncAttributeMaxDynamicSharedMemorySize, SMEM_PIPE);
    cudaFuncSetAttribute(wave2,    cudaFuncAttributeMaxDynamicSharedMemorySize, SMEM_OS);
    cudaFuncSetAttribute(tc_attn,  cudaFuncAttributeMaxDynamicSharedMemorySize, SMEM_OS);
    cudaFuncSetAttribute(tc_final, cudaFuncAttributeMaxDynamicSharedMemorySize, SMEM_PIPE);

    scalars_kernel<<<1, 1024>>>(gate, mnorm);

    cvt_all<<<12288, 256>>>((const float4*)hs, (const float4*)wq, (const float4*)wk,
                            (const float4*)wv, (const float4*)wo, mem);

    dim3 gP(DD/128, MTOT/128, 3);       // (8, 32, 3)
    tc_proj3<<<gP, 256, SMEM_PIPE>>>();

    normq_kernel<<<(MTOT*32 + 255)/256, 256>>>(mnorm);
    zc_kernel<<<(BSZ*NCH*DD + 255)/256, 256>>>();
    zprefix_kernel<<<(BSZ*DD + 255)/256, 256>>>();

    wave2<<<2336, 256, SMEM_OS>>>();
    wave3<<<8704, 256>>>();

    dim3 gAt(DD/128, 1, BSZ*NCH);       // (8, 1, 32)
    tc_attn<<<gAt, 256, SMEM_OS>>>();

    dim3 gM(DD/128, MTOT/128);          // (8, 32)
    tc_final<<<gM, 256, SMEM_PIPE>>>(out);
}

// round 16
// speedup vs baseline: 1.2558x; 1.0120x over previous
#include <cuda_runtime.h>
#include <cuda_fp16.h>
#include <math.h>
#include <stdint.h>

#define BSZ 2
#define SEQ 2048
#define DD 1024
#define CH 128
#define NCH 16
#define MTOT (BSZ*SEQ)        // 4096
#define EPSV 1e-6f

typedef __half hf;

// ---------------- scratch ----------------
__device__ float d_zz[BSZ*NCH*DD];
__device__ float d_den[BSZ*NCH*CH];
__device__ float d_normq[MTOT];
__device__ float d_scal[2];

// fp16 operand buffers
__device__ hf d_memouth[MTOT*DD];                // g*act*memout/normq (fp16)
__device__ hf d_hsh[MTOT*DD];
__device__ hf d_wqh[DD*DD];
__device__ hf d_wkh[DD*DD];
__device__ hf d_wvh[DD*DD];
__device__ hf d_woh[DD*DD];
__device__ hf d_memTh[DD*DD];
__device__ hf d_sqh[MTOT*DD];
__device__ hf d_skh[MTOT*DD];
__device__ hf d_vh [MTOT*DD];
__device__ hf d_Gh [(size_t)BSZ*NCH*DD*DD];      // per-chunk KV products
__device__ hf d_Sph[(size_t)BSZ*NCH*DD*DD];      // exclusive prefix of G
__device__ hf d_Abh[BSZ*NCH*CH*CH];
__device__ hf d_cmh[MTOT*DD];

// ---------------- small kernels ----------------
__global__ void scalars_kernel(const float* __restrict__ gate,
                               const float* __restrict__ mnorm) {
    __shared__ float sh[1024];
    int t = threadIdx.x;
    sh[t] = mnorm[t];
    __syncthreads();
    for (int s = 512; s > 0; s >>= 1) { if (t < s) sh[t] += sh[t+s]; __syncthreads(); }
    if (t == 0) {
        d_scal[0] = 1.f / (1.f + expf(-gate[0]));
        d_scal[1] = (sh[0] >= EPSV) ? 1.f : 0.f;
    }
}

__device__ __forceinline__ void cvt4hi(const float4* src, uint2* hi, int i) {
    float4 x = src[i];
    union { __half2 b[2]; uint2 u; } uh;
    uh.b[0] = __halves2half2(__float2half_rn(x.x), __float2half_rn(x.y));
    uh.b[1] = __halves2half2(__float2half_rn(x.z), __float2half_rn(x.w));
    hi[i] = uh.u;
}

// fused converts: hs | wq | wk | wv | wo | memT
__global__ void cvt_all(const float4* __restrict__ hs,
                        const float4* __restrict__ wq, const float4* __restrict__ wk,
                        const float4* __restrict__ wv, const float4* __restrict__ wo,
                        const float* __restrict__ mem) {
    int bid = blockIdx.x, tid = threadIdx.x;
    if (bid < 4096)        cvt4hi(hs, (uint2*)d_hsh, bid*256 + tid);
    else if (bid < 5120)   cvt4hi(wq, (uint2*)d_wqh, (bid-4096)*256 + tid);
    else if (bid < 6144)   cvt4hi(wk, (uint2*)d_wkh, (bid-5120)*256 + tid);
    else if (bid < 7168)   cvt4hi(wv, (uint2*)d_wvh, (bid-6144)*256 + tid);
    else if (bid < 8192)   cvt4hi(wo, (uint2*)d_woh, (bid-7168)*256 + tid);
    else {
        int idx = (bid-8192)*256 + tid;           // DD*DD
        int k = idx & (DD-1), n = idx >> 10;
        d_memTh[(size_t)n*DD + k] = __float2half_rn(mem[(size_t)k*DD + n]);
    }
}

// fused aux: normq (blocks 0..511) + zc (blocks 512..639); independent sections
__global__ void aux_kernel(const float* __restrict__ mnorm) {
    int bid = blockIdx.x, tid = threadIdx.x;
    if (bid < 512) {
        int warp = (bid*256 + tid) >> 5;
        int lane = tid & 31;
        if (warp >= MTOT) return;
        const hf* row = d_sqh + (size_t)warp * DD;
        float s = 0.f;
        for (int k = lane; k < DD; k += 32) s += __half2float(row[k]) * mnorm[k];
        #pragma unroll
        for (int o = 16; o > 0; o >>= 1) s += __shfl_xor_sync(0xffffffffu, s, o);
        if (lane == 0) d_normq[warp] = fmaxf(s, EPSV);
    } else {
        int idx = (bid - 512)*256 + tid;          // BSZ*NCH*DD = 32768
        int d = idx % DD; int bn = idx / DD;
        int b = bn >> 4, n = bn & 15;
        const hf* base = d_skh + (size_t)(b*SEQ + n*CH)*DD + d;
        float s = 0.f;
        #pragma unroll 4
        for (int i = 0; i < CH; ++i) s += __half2float(base[(size_t)i*DD]);
        d_zz[idx] = s;
    }
}

__global__ void zprefix_kernel() {
    int idx = blockIdx.x * blockDim.x + threadIdx.x;
    if (idx >= BSZ*DD) return;
    int b = idx / DD, d = idx % DD;
    float run = 0.f;
    for (int n = 0; n < NCH; ++n) {
        float* p = d_zz + (size_t)(b*NCH + n)*DD + d;
        float t = *p; *p = run; run += t;
    }
}

// ---------------- tensor-core GEMM core (pure fp16, K-step 32, 3-stage) ----------------
#define NT_STRIDE 40
#define T_STRIDE 136
#define MAT_B 10240
#define STAGE_B (2*MAT_B)     // 20480
#define SMEM_PIPE (3*STAGE_B) // 61440

// one-shot (K=128) layout: both matrices 128 rows x 136 halfs
#define OS_STRIDE 136
#define OS_MAT_B (128*OS_STRIDE*2)   // 34816
#define SMEM_OS (2*OS_MAT_B)         // 69632

__device__ __forceinline__ void cpa16(void* dst, const void* src) {
    uint32_t d = (uint32_t)__cvta_generic_to_shared(dst);
    asm volatile("cp.async.cg.shared.global [%0], [%1], 16;" :: "r"(d), "l"(src));
}
__device__ __forceinline__ void cp_commit() { asm volatile("cp.async.commit_group;"); }
__device__ __forceinline__ void cp_wait1()  { asm volatile("cp.async.wait_group 1;"); }
__device__ __forceinline__ void cp_wait0()  { asm volatile("cp.async.wait_group 0;"); }

__device__ __forceinline__ void ldsm4a(uint32_t* r, uint32_t a) {
    asm volatile("ldmatrix.sync.aligned.m8n8.x4.shared.b16 {%0,%1,%2,%3}, [%4];"
        : "=r"(r[0]), "=r"(r[1]), "=r"(r[2]), "=r"(r[3]) : "r"(a));
}
__device__ __forceinline__ void ldsm4ta(uint32_t* r, uint32_t a) {
    asm volatile("ldmatrix.sync.aligned.m8n8.x4.trans.shared.b16 {%0,%1,%2,%3}, [%4];"
        : "=r"(r[0]), "=r"(r[1]), "=r"(r[2]), "=r"(r[3]) : "r"(a));
}
__device__ __forceinline__ void mma_f16(float* c, const uint32_t* a, const uint32_t* b) {
    asm volatile("mma.sync.aligned.m16n8k16.row.col.f32.f16.f16.f32 "
        "{%0,%1,%2,%3}, {%4,%5,%6,%7}, {%8,%9}, {%0,%1,%2,%3};"
        : "+f"(c[0]), "+f"(c[1]), "+f"(c[2]), "+f"(c[3])
        : "r"(a[0]), "r"(a[1]), "r"(a[2]), "r"(a[3]), "r"(b[0]), "r"(b[1]));
}

struct Op { const hf* p; int ld; };

template<int TA, int TB>
__device__ __forceinline__ void stage(Op A, Op B, int k0, char* sm, int tid) {
    hf* Ah = (hf*)sm;
    hf* Bh = (hf*)(sm + MAT_B);
    #pragma unroll
    for (int i = 0; i < 2; ++i) {
        int idx = tid + 256*i;
        if (!TA) {
            int row = idx >> 2, ch = idx & 3;
            cpa16(Ah + row*NT_STRIDE + ch*8, A.p + (size_t)row*A.ld + k0 + ch*8);
        } else {
            int row = idx >> 4, ch = idx & 15;
            cpa16(Ah + row*T_STRIDE + ch*8, A.p + (size_t)(k0 + row)*A.ld + ch*8);
        }
        if (!TB) {
            int row = idx >> 2, ch = idx & 3;
            cpa16(Bh + row*NT_STRIDE + ch*8, B.p + (size_t)row*B.ld + k0 + ch*8);
        } else {
            int row = idx >> 4, ch = idx & 15;
            cpa16(Bh + row*T_STRIDE + ch*8, B.p + (size_t)(k0 + row)*B.ld + ch*8);
        }
    }
}

struct LaneOff {
    uint32_t a[2];
    uint32_t b[4];
};
template<int TA, int TB>
__device__ __forceinline__ LaneOff make_off(int lane, int wm, int wn) {
    LaneOff lo;
    #pragma unroll
    for (int mt = 0; mt < 2; ++mt) {
        lo.a[mt] = (!TA)
            ? (uint32_t)(((wm + mt*16 + (lane & 15))*NT_STRIDE + ((lane >> 4) << 3)) * 2)
            : (uint32_t)(((((lane >> 4) << 3) + (lane & 7))*T_STRIDE + wm + mt*16 + (lane & 8)) * 2);
    }
    #pragma unroll
    for (int nq = 0; nq < 4; ++nq) {
        lo.b[nq] = (!TB)
            ? (uint32_t)(MAT_B + ((wn + nq*16 + (lane & 15))*NT_STRIDE + ((lane >> 4) << 3)) * 2)
            : (uint32_t)(MAT_B + (((lane & 15))*T_STRIDE + wn + nq*16 + ((lane >> 4) << 3)) * 2);
    }
    return lo;
}

template<int TA, int TB>
__device__ __forceinline__ void compute16(uint32_t smaddr, int ks, const LaneOff& lo,
                                          float acc[2][8][4]) {
    const uint32_t dA = (!TA) ? (uint32_t)(2*ks) : (uint32_t)(2*ks*T_STRIDE);
    const uint32_t dB = (!TB) ? (uint32_t)(2*ks) : (uint32_t)(2*ks*T_STRIDE);
    uint32_t ah[2][4], bh[8][2];
    #pragma unroll
    for (int mt = 0; mt < 2; ++mt) {
        uint32_t a = smaddr + lo.a[mt] + dA;
        if (!TA) ldsm4a(ah[mt], a); else ldsm4ta(ah[mt], a);
    }
    #pragma unroll
    for (int nq = 0; nq < 4; ++nq) {
        uint32_t a = smaddr + lo.b[nq] + dB;
        uint32_t r[4];
        if (!TB) {
            ldsm4a(r, a);
            bh[2*nq][0]=r[0]; bh[2*nq][1]=r[2]; bh[2*nq+1][0]=r[1]; bh[2*nq+1][1]=r[3];
        } else {
            ldsm4ta(r, a);
            bh[2*nq][0]=r[0]; bh[2*nq][1]=r[1]; bh[2*nq+1][0]=r[2]; bh[2*nq+1][1]=r[3];
        }
    }
    #pragma unroll
    for (int mt = 0; mt < 2; ++mt)
        #pragma unroll
        for (int nt = 0; nt < 8; ++nt)
            mma_f16(acc[mt][nt], ah[mt], bh[nt]);
}

// 3-stage pipeline (K multiple of 32, KT>=4): one __syncthreads per k-iter.
template<int TA, int TB>
__device__ __forceinline__ void gemm_core(Op A, Op B, int K, float acc[2][8][4],
                                          char* smbase, int tid) {
    const int lane = tid & 31, wid = tid >> 5;
    const int wm = (wid & 3) * 32, wn = (wid >> 2) * 64;
    const LaneOff lo = make_off<TA,TB>(lane, wm, wn);
    const uint32_t base0 = (uint32_t)__cvta_generic_to_shared(smbase);
    const int KT = K >> 5;
    stage<TA,TB>(A, B, 0, smbase, tid);            cp_commit();
    stage<TA,TB>(A, B, 32, smbase + STAGE_B, tid); cp_commit();
    int buf = 0;
    for (int kt = 0; kt < KT; ++kt) {
        if (kt + 1 < KT) cp_wait1(); else cp_wait0();
        __syncthreads();
        uint32_t cur = base0 + (uint32_t)(buf*STAGE_B);
        compute16<TA,TB>(cur, 0,  lo, acc);
        compute16<TA,TB>(cur, 16, lo, acc);
        if (kt + 2 < KT) {
            int nb = buf + 2; if (nb >= 3) nb -= 3;
            stage<TA,TB>(A, B, (kt+2) << 5, smbase + nb*STAGE_B, tid);
            cp_commit();
        }
        buf = (buf + 1 == 3) ? 0 : buf + 1;
    }
    __syncthreads();
}

// ---- one-shot K=128 path ----
template<int TA, int TB>
__device__ __forceinline__ void compute16o(uint32_t smaddr, int ks, int lane,
                                           int wm, int wn, float acc[2][8][4]) {
    uint32_t ah[2][4], bh[8][2];
    #pragma unroll
    for (int mt = 0; mt < 2; ++mt) {
        uint32_t a;
        if (!TA) {
            a = smaddr + (uint32_t)(((wm + mt*16 + (lane & 15))*OS_STRIDE + ks + ((lane >> 4) << 3)) * 2);
            ldsm4a(ah[mt], a);
        } else {
            a = smaddr + (uint32_t)(((ks + ((lane >> 4) << 3) + (lane & 7))*OS_STRIDE + wm + mt*16 + (lane & 8)) * 2);
            ldsm4ta(ah[mt], a);
        }
    }
    #pragma unroll
    for (int nq = 0; nq < 4; ++nq) {
        uint32_t a;
        uint32_t r[4];
        if (!TB) {
            a = smaddr + (uint32_t)(OS_MAT_B + ((wn + nq*16 + (lane & 15))*OS_STRIDE + ks + ((lane >> 4) << 3)) * 2);
            ldsm4a(r, a);
            bh[2*nq][0]=r[0]; bh[2*nq][1]=r[2]; bh[2*nq+1][0]=r[1]; bh[2*nq+1][1]=r[3];
        } else {
            a = smaddr + (uint32_t)(OS_MAT_B + ((ks + (lane & 15))*OS_STRIDE + wn + nq*16 + ((lane >> 4) << 3)) * 2);
            ldsm4ta(r, a);
            bh[2*nq][0]=r[0]; bh[2*nq][1]=r[1]; bh[2*nq+1][0]=r[2]; bh[2*nq+1][1]=r[3];
        }
    }
    #pragma unroll
    for (int mt = 0; mt < 2; ++mt)
        #pragma unroll
        for (int nt = 0; nt < 8; ++nt)
            mma_f16(acc[mt][nt], ah[mt], bh[nt]);
}

template<int TA, int TB>
__device__ __forceinline__ void gemm_once(Op A, Op B, float acc[2][8][4],
                                          char* smbase, int tid) {
    hf* Ah = (hf*)smbase;
    hf* Bh = (hf*)(smbase + OS_MAT_B);
    #pragma unroll
    for (int i = 0; i < 8; ++i) {
        int idx = tid + 256*i;
        int row = idx >> 4, ch = idx & 15;
        cpa16(Ah + row*OS_STRIDE + ch*8, A.p + (size_t)row*A.ld + ch*8);
        cpa16(Bh + row*OS_STRIDE + ch*8, B.p + (size_t)row*B.ld + ch*8);
    }
    cp_commit();
    cp_wait0();
    __syncthreads();
    const int lane = tid & 31, wid = tid >> 5;
    const int wm = (wid & 3) * 32, wn = (wid >> 2) * 64;
    const uint32_t base = (uint32_t)__cvta_generic_to_shared(smbase);
    #pragma unroll
    for (int ks = 0; ks < 128; ks += 16)
        compute16o<TA,TB>(base, ks, lane, wm, wn, acc);
    __syncthreads();
}

#define GEMM_SMEM extern __shared__ char sm_[];

#define EPI_COORDS \
    const int lane = tid & 31, wid = tid >> 5; \
    const int gid = lane >> 2, tig = lane & 3; \
    const int wm = (wid & 3) * 32, wn = (wid >> 2) * 64;

#define EPI_LOOP(BODY) \
    _Pragma("unroll") for (int mt = 0; mt < 2; ++mt) \
    _Pragma("unroll") for (int nt = 0; nt < 8; ++nt) \
    _Pragma("unroll") for (int ci = 0; ci < 4; ++ci) { \
        int mr = wm + mt*16 + gid + ((ci >> 1) ? 8 : 0); \
        int nr = wn + nt*8 + tig*2 + (ci & 1); \
        float v = acc[mt][nt][ci]; \
        BODY \
    }

// ---------------- GEMM kernels ----------------
__global__ void __launch_bounds__(256, 2) tc_proj3() {
    GEMM_SMEM;
    int tid = threadIdx.x;
    int m0 = blockIdx.y * 128, n0 = blockIdx.x * 128;
    int which = blockIdx.z;
    const hf* wh = (which==0) ? d_wqh : (which==1) ? d_wkh : d_wvh;
    float acc[2][8][4] = {};
    Op A{d_hsh + (size_t)m0*DD, DD};
    Op B{wh + (size_t)n0*DD, DD};
    gemm_core<0,0>(A, B, DD, acc, sm_, tid);
    EPI_COORDS;
    if (which == 0) {
        EPI_LOOP({
            size_t o = (size_t)(m0+mr)*DD + n0 + nr;
            v = (v > 0.f) ? v + 1.f : expf(v);
            d_sqh[o] = __float2half_rn(v);
        })
    } else if (which == 1) {
        EPI_LOOP({
            size_t o = (size_t)(m0+mr)*DD + n0 + nr;
            v = (v > 0.f) ? v + 1.f : expf(v);
            d_skh[o] = __float2half_rn(v);
        })
    } else {
        EPI_LOOP({
            size_t o = (size_t)(m0+mr)*DD + n0 + nr;
            d_vh[o] = __float2half_rn(v);
        })
    }
}

// fused wave2: kv 2048 (one-shot) | memout 256 | scores 32
__global__ void __launch_bounds__(256, 2) wave2() {
    GEMM_SMEM;
    int tid = threadIdx.x;
    int bid = blockIdx.x;
    if (bid < 2048) {
        int bn = bid >> 6, loc = bid & 63;
        int b = bn >> 4, n = bn & 15;
        size_t cb = (size_t)(b*SEQ + n*CH)*DD;
        int m0 = (loc >> 3) * 128, n0 = (loc & 7) * 128;
        float acc[2][8][4] = {};
        Op A{d_skh + cb + m0, DD};
        Op B{d_vh + cb + n0, DD};
        gemm_once<1,1>(A, B, acc, sm_, tid);
        hf* C = d_Gh + (size_t)bn*DD*DD;
        EPI_COORDS;
        EPI_LOOP({
            C[(size_t)(m0+mr)*DD + n0 + nr] = __float2half_rn(v);
        })
    } else if (bid < 2304) {
        int idx = bid - 2048;
        int m0 = (idx >> 3) * 128, n0 = (idx & 7) * 128;
        float acc[2][8][4] = {};
        Op A{d_sqh + (size_t)m0*DD, DD};
        Op B{d_memTh + (size_t)n0*DD, DD};
        gemm_core<0,0>(A, B, DD, acc, sm_, tid);
        float gs = d_scal[0] * d_scal[1];
        EPI_COORDS;
        EPI_LOOP({
            d_memouth[(size_t)(m0+mr)*DD + n0 + nr] =
                __float2half_rn(v * gs / d_normq[m0+mr]);
        })
    } else {
        int bn = bid - 2304;
        int b = bn >> 4, n = bn & 15;
        size_t cb = (size_t)(b*SEQ + n*CH)*DD;
        float acc[2][8][4] = {};
        Op A{d_sqh + cb, DD};
        Op B{d_skh + cb, DD};
        gemm_core<0,0>(A, B, DD, acc, sm_, tid);
        size_t co = (size_t)bn*CH*CH;
        EPI_COORDS;
        EPI_LOOP({
            float m = (nr <= mr) ? v : 0.f;
            d_Abh[co + (size_t)mr*CH + nr] = __float2half_rn(m);
        })
    }
}

// fused wave3: gprefix (8192 blocks) + den (512 blocks, fp16 Abh)
__global__ void __launch_bounds__(256) wave3() {
    int bid = blockIdx.x, tid = threadIdx.x;
    if (bid < 8192) {
        size_t idx = (size_t)bid*256 + tid;
        int b = (int)(idx / ((size_t)DD*DD));
        size_t rem = idx % ((size_t)DD*DD);
        float run = 0.f;
        for (int n = 0; n < NCH; ++n) {
            size_t off = ((size_t)(b*NCH + n)*DD*DD) + rem;
            float t = __half2float(d_Gh[off]);
            d_Sph[off] = __float2half_rn(run);
            run += t;
        }
    } else {
        int warp = ((bid - 8192)*256 + tid) >> 5;
        int lane = tid & 31;
        if (warp >= BSZ*NCH*CH) return;
        int bn = warp / CH, i = warp % CH;
        int b = bn >> 4, n = bn & 15;
        const hf* qr = d_sqh + (size_t)(b*SEQ + n*CH + i)*DD;
        const float* zr = d_zz + (size_t)bn*DD;
        float s = 0.f;
        for (int k = lane; k < DD; k += 32) s += __half2float(qr[k]) * zr[k];
        const hf* ar = d_Abh + (size_t)bn*CH*CH + (size_t)i*CH;
        for (int j = lane; j < CH; j += 32) s += __half2float(ar[j]);
        #pragma unroll
        for (int o = 16; o > 0; o >>= 1) s += __shfl_xor_sync(0xffffffffu, s, o);
        if (lane == 0) d_den[warp] = fmaxf(s, EPSV);
    }
}

// attn: local = (sq @ Sp + Abuf @ v)/den; phase2 one-shot; combine fused -> d_cmh
__global__ void __launch_bounds__(256, 2) tc_attn() {
    GEMM_SMEM;
    int tid = threadIdx.x;
    int bn = blockIdx.z; int b = bn >> 4, n = bn & 15;
    size_t cb = (size_t)(b*SEQ + n*CH)*DD;
    int n0 = blockIdx.x * 128;
    float acc[2][8][4] = {};
    {
        Op A{d_sqh + cb, DD};
        Op B{d_Sph + (size_t)bn*DD*DD + n0, DD};   // trans [d][e]
        gemm_core<0,1>(A, B, DD, acc, sm_, tid);
    }
    {
        Op A{d_Abh + (size_t)bn*CH*CH, CH};
        Op B{d_vh + cb + n0, DD};                  // trans [c][e]
        gemm_once<0,1>(A, B, acc, sm_, tid);
    }
    float og = 1.f - d_scal[0];
    EPI_COORDS;
    EPI_LOOP({
        size_t o = cb + (size_t)mr*DD + n0 + nr;
        float cm = __half2float(d_memouth[o]) + og * v / d_den[bn*CH + mr];
        d_cmh[o] = __float2half_rn(cm);
    })
}

__global__ void __launch_bounds__(256, 2) tc_final(float* __restrict__ Out) {
    GEMM_SMEM;
    int tid = threadIdx.x;
    int m0 = blockIdx.y * 128, n0 = blockIdx.x * 128;
    float acc[2][8][4] = {};
    Op A{d_cmh + (size_t)m0*DD, DD};
    Op B{d_woh + (size_t)n0*DD, DD};
    gemm_core<0,0>(A, B, DD, acc, sm_, tid);
    EPI_COORDS;
    EPI_LOOP({
        Out[(size_t)(m0+mr)*DD + n0 + nr] = v;
    })
}

// ---------------- launcher ----------------
extern "C" void kernel_launch(void* const* d_in, const int* in_sizes, int n_in,
                              void* d_out, int out_size) {
    const float* hs    = (const float*)d_in[0];
    const float* wq    = (const float*)d_in[1];
    const float* wk    = (const float*)d_in[2];
    const float* wv    = (const float*)d_in[3];
    const float* wo    = (const float*)d_in[4];
    const float* gate  = (const float*)d_in[5];
    const float* mem   = (const float*)d_in[6];
    const float* mnorm = (const float*)d_in[7];
    float* out = (float*)d_out;

    cudaFuncSetAttribute(tc_proj3, cudaFuncAttributeMaxDynamicSharedMemorySize, SMEM_PIPE);
    cudaFuncSetAttribute(wave2,    cudaFuncAttributeMaxDynamicSharedMemorySize, SMEM_OS);
    cudaFuncSetAttribute(tc_attn,  cudaFuncAttributeMaxDynamicSharedMemorySize, SMEM_OS);
    cudaFuncSetAttribute(tc_final, cudaFuncAttributeMaxDynamicSharedMemorySize, SMEM_PIPE);

    scalars_kernel<<<1, 1024>>>(gate, mnorm);

    cvt_all<<<12288, 256>>>((const float4*)hs, (const float4*)wq, (const float4*)wk,
                            (const float4*)wv, (const float4*)wo, mem);

    dim3 gP(DD/128, MTOT/128, 3);       // (8, 32, 3)
    tc_proj3<<<gP, 256, SMEM_PIPE>>>();

    aux_kernel<<<640, 256>>>(mnorm);    // normq + zc
    zprefix_kernel<<<(BSZ*DD + 255)/256, 256>>>();

    wave2<<<2336, 256, SMEM_OS>>>();
    wave3<<<8704, 256>>>();

    dim3 gAt(DD/128, 1, BSZ*NCH);       // (8, 1, 32)
    tc_attn<<<gAt, 256, SMEM_OS>>>();

    dim3 gM(DD/128, MTOT/128);          // (8, 32)
    tc_final<<<gM, 256, SMEM_PIPE>>>(out);
}

// round 17
// speedup vs baseline: 1.5663x; 1.2472x over previous
#include <cuda_runtime.h>
#include <cuda_fp16.h>
#include <math.h>
#include <stdint.h>

#define BSZ 2
#define SEQ 2048
#define DD 1024
#define CH 128
#define NCH 16
#define MTOT (BSZ*SEQ)        // 4096
#define EPSV 1e-6f

typedef __half hf;

// ---------------- scratch ----------------
__device__ float d_zz[BSZ*NCH*DD];
__device__ float d_den[BSZ*NCH*CH];
__device__ float d_normq[MTOT];
__device__ float d_scal[2];

// fp16 operand buffers
__device__ hf d_memouth[MTOT*DD];
__device__ hf d_hsh[MTOT*DD];
__device__ hf d_wqh[DD*DD];
__device__ hf d_wkh[DD*DD];
__device__ hf d_wvh[DD*DD];
__device__ hf d_woh[DD*DD];
__device__ hf d_memTh[DD*DD];
__device__ hf d_sqh[MTOT*DD];
__device__ hf d_skh[MTOT*DD];
__device__ hf d_vh [MTOT*DD];
__device__ hf d_Gh [(size_t)BSZ*NCH*DD*DD];
__device__ hf d_Sph[(size_t)BSZ*NCH*DD*DD];
__device__ hf d_Abh[BSZ*NCH*CH*CH];
__device__ hf d_cmh[MTOT*DD];

// ---------------- small kernels ----------------
__global__ void scalars_kernel(const float* __restrict__ gate,
                               const float* __restrict__ mnorm) {
    __shared__ float sh[1024];
    int t = threadIdx.x;
    sh[t] = mnorm[t];
    __syncthreads();
    for (int s = 512; s > 0; s >>= 1) { if (t < s) sh[t] += sh[t+s]; __syncthreads(); }
    if (t == 0) {
        d_scal[0] = 1.f / (1.f + expf(-gate[0]));
        d_scal[1] = (sh[0] >= EPSV) ? 1.f : 0.f;
    }
}

__device__ __forceinline__ void cvt4hi(const float4* src, uint2* hi, int i) {
    float4 x = src[i];
    union { __half2 b[2]; uint2 u; } uh;
    uh.b[0] = __halves2half2(__float2half_rn(x.x), __float2half_rn(x.y));
    uh.b[1] = __halves2half2(__float2half_rn(x.z), __float2half_rn(x.w));
    hi[i] = uh.u;
}

// fused converts: hs | wq | wk | wv | wo | memT
__global__ void cvt_all(const float4* __restrict__ hs,
                        const float4* __restrict__ wq, const float4* __restrict__ wk,
                        const float4* __restrict__ wv, const float4* __restrict__ wo,
                        const float* __restrict__ mem) {
    int bid = blockIdx.x, tid = threadIdx.x;
    if (bid < 4096)        cvt4hi(hs, (uint2*)d_hsh, bid*256 + tid);
    else if (bid < 5120)   cvt4hi(wq, (uint2*)d_wqh, (bid-4096)*256 + tid);
    else if (bid < 6144)   cvt4hi(wk, (uint2*)d_wkh, (bid-5120)*256 + tid);
    else if (bid < 7168)   cvt4hi(wv, (uint2*)d_wvh, (bid-6144)*256 + tid);
    else if (bid < 8192)   cvt4hi(wo, (uint2*)d_woh, (bid-7168)*256 + tid);
    else {
        int idx = (bid-8192)*256 + tid;
        int k = idx & (DD-1), n = idx >> 10;
        d_memTh[(size_t)n*DD + k] = __float2half_rn(mem[(size_t)k*DD + n]);
    }
}

// fused aux: normq (blocks 0..511) + vectorized zc (blocks 512..575)
__global__ void aux_kernel(const float* __restrict__ mnorm) {
    int bid = blockIdx.x, tid = threadIdx.x;
    if (bid < 512) {
        int warp = (bid*256 + tid) >> 5;
        int lane = tid & 31;
        if (warp >= MTOT) return;
        const __half2* row = (const __half2*)(d_sqh + (size_t)warp * DD);
        const float2* mn2 = (const float2*)mnorm;
        float s = 0.f;
        for (int k = lane; k < DD/2; k += 32) {
            __half2 h = row[k];
            float2 m = mn2[k];
            s += __low2float(h) * m.x + __high2float(h) * m.y;
        }
        #pragma unroll
        for (int o = 16; o > 0; o >>= 1) s += __shfl_xor_sync(0xffffffffu, s, o);
        if (lane == 0) d_normq[warp] = fmaxf(s, EPSV);
    } else {
        int idx = (bid - 512)*256 + tid;          // BSZ*NCH*DD/2 = 16384
        int d2 = idx % (DD/2); int bn = idx / (DD/2);
        int b = bn >> 4, n = bn & 15;
        const __half2* base = (const __half2*)(d_skh + (size_t)(b*SEQ + n*CH)*DD) + d2;
        float sx = 0.f, sy = 0.f;
        #pragma unroll 4
        for (int i = 0; i < CH; ++i) {
            __half2 h = base[(size_t)i*(DD/2)];
            sx += __low2float(h); sy += __high2float(h);
        }
        d_zz[bn*DD + 2*d2]     = sx;
        d_zz[bn*DD + 2*d2 + 1] = sy;
    }
}

__global__ void zprefix_kernel() {
    int idx = blockIdx.x * blockDim.x + threadIdx.x;
    if (idx >= BSZ*DD) return;
    int b = idx / DD, d = idx % DD;
    float run = 0.f;
    for (int n = 0; n < NCH; ++n) {
        float* p = d_zz + (size_t)(b*NCH + n)*DD + d;
        float t = *p; *p = run; run += t;
    }
}

// ---------------- tensor-core GEMM core (pure fp16, K-step 32, 3-stage) ----------------
#define NT_STRIDE 40
#define T_STRIDE 136
#define MAT_B 10240
#define STAGE_B (2*MAT_B)     // 20480
#define SMEM_PIPE (3*STAGE_B) // 61440

#define OS_STRIDE 136
#define OS_MAT_B (128*OS_STRIDE*2)   // 34816
#define SMEM_OS (2*OS_MAT_B)         // 69632

__device__ __forceinline__ void cpa16(void* dst, const void* src) {
    uint32_t d = (uint32_t)__cvta_generic_to_shared(dst);
    asm volatile("cp.async.cg.shared.global [%0], [%1], 16;" :: "r"(d), "l"(src));
}
__device__ __forceinline__ void cp_commit() { asm volatile("cp.async.commit_group;"); }
__device__ __forceinline__ void cp_wait1()  { asm volatile("cp.async.wait_group 1;"); }
__device__ __forceinline__ void cp_wait0()  { asm volatile("cp.async.wait_group 0;"); }

__device__ __forceinline__ void ldsm4a(uint32_t* r, uint32_t a) {
    asm volatile("ldmatrix.sync.aligned.m8n8.x4.shared.b16 {%0,%1,%2,%3}, [%4];"
        : "=r"(r[0]), "=r"(r[1]), "=r"(r[2]), "=r"(r[3]) : "r"(a));
}
__device__ __forceinline__ void ldsm4ta(uint32_t* r, uint32_t a) {
    asm volatile("ldmatrix.sync.aligned.m8n8.x4.trans.shared.b16 {%0,%1,%2,%3}, [%4];"
        : "=r"(r[0]), "=r"(r[1]), "=r"(r[2]), "=r"(r[3]) : "r"(a));
}
__device__ __forceinline__ void mma_f16(float* c, const uint32_t* a, const uint32_t* b) {
    asm volatile("mma.sync.aligned.m16n8k16.row.col.f32.f16.f16.f32 "
        "{%0,%1,%2,%3}, {%4,%5,%6,%7}, {%8,%9}, {%0,%1,%2,%3};"
        : "+f"(c[0]), "+f"(c[1]), "+f"(c[2]), "+f"(c[3])
        : "r"(a[0]), "r"(a[1]), "r"(a[2]), "r"(a[3]), "r"(b[0]), "r"(b[1]));
}

struct Op { const hf* p; int ld; };

template<int TA, int TB>
__device__ __forceinline__ void stage(Op A, Op B, int k0, char* sm, int tid) {
    hf* Ah = (hf*)sm;
    hf* Bh = (hf*)(sm + MAT_B);
    #pragma unroll
    for (int i = 0; i < 2; ++i) {
        int idx = tid + 256*i;
        if (!TA) {
            int row = idx >> 2, ch = idx & 3;
            cpa16(Ah + row*NT_STRIDE + ch*8, A.p + (size_t)row*A.ld + k0 + ch*8);
        } else {
            int row = idx >> 4, ch = idx & 15;
            cpa16(Ah + row*T_STRIDE + ch*8, A.p + (size_t)(k0 + row)*A.ld + ch*8);
        }
        if (!TB) {
            int row = idx >> 2, ch = idx & 3;
            cpa16(Bh + row*NT_STRIDE + ch*8, B.p + (size_t)row*B.ld + k0 + ch*8);
        } else {
            int row = idx >> 4, ch = idx & 15;
            cpa16(Bh + row*T_STRIDE + ch*8, B.p + (size_t)(k0 + row)*B.ld + ch*8);
        }
    }
}

struct LaneOff {
    uint32_t a[2];
    uint32_t b[4];
};
template<int TA, int TB>
__device__ __forceinline__ LaneOff make_off(int lane, int wm, int wn) {
    LaneOff lo;
    #pragma unroll
    for (int mt = 0; mt < 2; ++mt) {
        lo.a[mt] = (!TA)
            ? (uint32_t)(((wm + mt*16 + (lane & 15))*NT_STRIDE + ((lane >> 4) << 3)) * 2)
            : (uint32_t)(((((lane >> 4) << 3) + (lane & 7))*T_STRIDE + wm + mt*16 + (lane & 8)) * 2);
    }
    #pragma unroll
    for (int nq = 0; nq < 4; ++nq) {
        lo.b[nq] = (!TB)
            ? (uint32_t)(MAT_B + ((wn + nq*16 + (lane & 15))*NT_STRIDE + ((lane >> 4) << 3)) * 2)
            : (uint32_t)(MAT_B + (((lane & 15))*T_STRIDE + wn + nq*16 + ((lane >> 4) << 3)) * 2);
    }
    return lo;
}

template<int TA, int TB>
__device__ __forceinline__ void compute16(uint32_t smaddr, int ks, const LaneOff& lo,
                                          float acc[2][8][4]) {
    const uint32_t dA = (!TA) ? (uint32_t)(2*ks) : (uint32_t)(2*ks*T_STRIDE);
    const uint32_t dB = (!TB) ? (uint32_t)(2*ks) : (uint32_t)(2*ks*T_STRIDE);
    uint32_t ah[2][4], bh[8][2];
    #pragma unroll
    for (int mt = 0; mt < 2; ++mt) {
        uint32_t a = smaddr + lo.a[mt] + dA;
        if (!TA) ldsm4a(ah[mt], a); else ldsm4ta(ah[mt], a);
    }
    #pragma unroll
    for (int nq = 0; nq < 4; ++nq) {
        uint32_t a = smaddr + lo.b[nq] + dB;
        uint32_t r[4];
        if (!TB) {
            ldsm4a(r, a);
            bh[2*nq][0]=r[0]; bh[2*nq][1]=r[2]; bh[2*nq+1][0]=r[1]; bh[2*nq+1][1]=r[3];
        } else {
            ldsm4ta(r, a);
            bh[2*nq][0]=r[0]; bh[2*nq][1]=r[1]; bh[2*nq+1][0]=r[2]; bh[2*nq+1][1]=r[3];
        }
    }
    #pragma unroll
    for (int mt = 0; mt < 2; ++mt)
        #pragma unroll
        for (int nt = 0; nt < 8; ++nt)
            mma_f16(acc[mt][nt], ah[mt], bh[nt]);
}

template<int TA, int TB>
__device__ __forceinline__ void gemm_core(Op A, Op B, int K, float acc[2][8][4],
                                          char* smbase, int tid) {
    const int lane = tid & 31, wid = tid >> 5;
    const int wm = (wid & 3) * 32, wn = (wid >> 2) * 64;
    const LaneOff lo = make_off<TA,TB>(lane, wm, wn);
    const uint32_t base0 = (uint32_t)__cvta_generic_to_shared(smbase);
    const int KT = K >> 5;
    stage<TA,TB>(A, B, 0, smbase, tid);            cp_commit();
    stage<TA,TB>(A, B, 32, smbase + STAGE_B, tid); cp_commit();
    int buf = 0;
    for (int kt = 0; kt < KT; ++kt) {
        if (kt + 1 < KT) cp_wait1(); else cp_wait0();
        __syncthreads();
        uint32_t cur = base0 + (uint32_t)(buf*STAGE_B);
        compute16<TA,TB>(cur, 0,  lo, acc);
        compute16<TA,TB>(cur, 16, lo, acc);
        if (kt + 2 < KT) {
            int nb = buf + 2; if (nb >= 3) nb -= 3;
            stage<TA,TB>(A, B, (kt+2) << 5, smbase + nb*STAGE_B, tid);
            cp_commit();
        }
        buf = (buf + 1 == 3) ? 0 : buf + 1;
    }
    __syncthreads();
}

// ---- one-shot K=128 path ----
template<int TA, int TB>
__device__ __forceinline__ void compute16o(uint32_t smaddr, int ks, int lane,
                                           int wm, int wn, float acc[2][8][4]) {
    uint32_t ah[2][4], bh[8][2];
    #pragma unroll
    for (int mt = 0; mt < 2; ++mt) {
        uint32_t a;
        if (!TA) {
            a = smaddr + (uint32_t)(((wm + mt*16 + (lane & 15))*OS_STRIDE + ks + ((lane >> 4) << 3)) * 2);
            ldsm4a(ah[mt], a);
        } else {
            a = smaddr + (uint32_t)(((ks + ((lane >> 4) << 3) + (lane & 7))*OS_STRIDE + wm + mt*16 + (lane & 8)) * 2);
            ldsm4ta(ah[mt], a);
        }
    }
    #pragma unroll
    for (int nq = 0; nq < 4; ++nq) {
        uint32_t a;
        uint32_t r[4];
        if (!TB) {
            a = smaddr + (uint32_t)(OS_MAT_B + ((wn + nq*16 + (lane & 15))*OS_STRIDE + ks + ((lane >> 4) << 3)) * 2);
            ldsm4a(r, a);
            bh[2*nq][0]=r[0]; bh[2*nq][1]=r[2]; bh[2*nq+1][0]=r[1]; bh[2*nq+1][1]=r[3];
        } else {
            a = smaddr + (uint32_t)(OS_MAT_B + ((ks + (lane & 15))*OS_STRIDE + wn + nq*16 + ((lane >> 4) << 3)) * 2);
            ldsm4ta(r, a);
            bh[2*nq][0]=r[0]; bh[2*nq][1]=r[1]; bh[2*nq+1][0]=r[2]; bh[2*nq+1][1]=r[3];
        }
    }
    #pragma unroll
    for (int mt = 0; mt < 2; ++mt)
        #pragma unroll
        for (int nt = 0; nt < 8; ++nt)
            mma_f16(acc[mt][nt], ah[mt], bh[nt]);
}

template<int TA, int TB>
__device__ __forceinline__ void gemm_once(Op A, Op B, float acc[2][8][4],
                                          char* smbase, int tid) {
    hf* Ah = (hf*)smbase;
    hf* Bh = (hf*)(smbase + OS_MAT_B);
    #pragma unroll
    for (int i = 0; i < 8; ++i) {
        int idx = tid + 256*i;
        int row = idx >> 4, ch = idx & 15;
        cpa16(Ah + row*OS_STRIDE + ch*8, A.p + (size_t)row*A.ld + ch*8);
        cpa16(Bh + row*OS_STRIDE + ch*8, B.p + (size_t)row*B.ld + ch*8);
    }
    cp_commit();
    cp_wait0();
    __syncthreads();
    const int lane = tid & 31, wid = tid >> 5;
    const int wm = (wid & 3) * 32, wn = (wid >> 2) * 64;
    const uint32_t base = (uint32_t)__cvta_generic_to_shared(smbase);
    #pragma unroll
    for (int ks = 0; ks < 128; ks += 16)
        compute16o<TA,TB>(base, ks, lane, wm, wn, acc);
    __syncthreads();
}

#define GEMM_SMEM extern __shared__ char sm_[];

#define EPI_COORDS \
    const int lane = tid & 31, wid = tid >> 5; \
    const int gid = lane >> 2, tig = lane & 3; \
    const int wm = (wid & 3) * 32, wn = (wid >> 2) * 64;

// paired epilogue: v0,v1 at (mr, nr),(mr, nr+1); nr even
#define EPI_LOOP2(BODY) \
    _Pragma("unroll") for (int mt = 0; mt < 2; ++mt) \
    _Pragma("unroll") for (int nt = 0; nt < 8; ++nt) \
    _Pragma("unroll") for (int cp = 0; cp < 2; ++cp) { \
        int mr = wm + mt*16 + gid + (cp ? 8 : 0); \
        int nr = wn + nt*8 + tig*2; \
        float v0 = acc[mt][nt][2*cp]; \
        float v1 = acc[mt][nt][2*cp + 1]; \
        BODY \
    }

__device__ __forceinline__ void st_h2(hf* p, float a, float b) {
    *(__half2*)p = __halves2half2(__float2half_rn(a), __float2half_rn(b));
}

// ---------------- GEMM kernels ----------------
__global__ void __launch_bounds__(256, 2) tc_proj3() {
    GEMM_SMEM;
    int tid = threadIdx.x;
    int m0 = blockIdx.y * 128, n0 = blockIdx.x * 128;
    int which = blockIdx.z;
    const hf* wh = (which==0) ? d_wqh : (which==1) ? d_wkh : d_wvh;
    float acc[2][8][4] = {};
    Op A{d_hsh + (size_t)m0*DD, DD};
    Op B{wh + (size_t)n0*DD, DD};
    gemm_core<0,0>(A, B, DD, acc, sm_, tid);
    EPI_COORDS;
    if (which == 0) {
        EPI_LOOP2({
            size_t o = (size_t)(m0+mr)*DD + n0 + nr;
            v0 = (v0 > 0.f) ? v0 + 1.f : expf(v0);
            v1 = (v1 > 0.f) ? v1 + 1.f : expf(v1);
            st_h2(d_sqh + o, v0, v1);
        })
    } else if (which == 1) {
        EPI_LOOP2({
            size_t o = (size_t)(m0+mr)*DD + n0 + nr;
            v0 = (v0 > 0.f) ? v0 + 1.f : expf(v0);
            v1 = (v1 > 0.f) ? v1 + 1.f : expf(v1);
            st_h2(d_skh + o, v0, v1);
        })
    } else {
        EPI_LOOP2({
            size_t o = (size_t)(m0+mr)*DD + n0 + nr;
            st_h2(d_vh + o, v0, v1);
        })
    }
}

// fused wave2: kv 2048 (one-shot) | memout 256 | scores 32
__global__ void __launch_bounds__(256, 2) wave2() {
    GEMM_SMEM;
    int tid = threadIdx.x;
    int bid = blockIdx.x;
    if (bid < 2048) {
        int bn = bid >> 6, loc = bid & 63;
        int b = bn >> 4, n = bn & 15;
        size_t cb = (size_t)(b*SEQ + n*CH)*DD;
        int m0 = (loc >> 3) * 128, n0 = (loc & 7) * 128;
        float acc[2][8][4] = {};
        Op A{d_skh + cb + m0, DD};
        Op B{d_vh + cb + n0, DD};
        gemm_once<1,1>(A, B, acc, sm_, tid);
        hf* C = d_Gh + (size_t)bn*DD*DD;
        EPI_COORDS;
        EPI_LOOP2({
            st_h2(C + (size_t)(m0+mr)*DD + n0 + nr, v0, v1);
        })
    } else if (bid < 2304) {
        int idx = bid - 2048;
        int m0 = (idx >> 3) * 128, n0 = (idx & 7) * 128;
        float acc[2][8][4] = {};
        Op A{d_sqh + (size_t)m0*DD, DD};
        Op B{d_memTh + (size_t)n0*DD, DD};
        gemm_core<0,0>(A, B, DD, acc, sm_, tid);
        float gs = d_scal[0] * d_scal[1];
        EPI_COORDS;
        EPI_LOOP2({
            float inv = gs / d_normq[m0+mr];
            st_h2(d_memouth + (size_t)(m0+mr)*DD + n0 + nr, v0 * inv, v1 * inv);
        })
    } else {
        int bn = bid - 2304;
        int b = bn >> 4, n = bn & 15;
        size_t cb = (size_t)(b*SEQ + n*CH)*DD;
        float acc[2][8][4] = {};
        Op A{d_sqh + cb, DD};
        Op B{d_skh + cb, DD};
        gemm_core<0,0>(A, B, DD, acc, sm_, tid);
        size_t co = (size_t)bn*CH*CH;
        EPI_COORDS;
        EPI_LOOP2({
            float a0 = (nr     <= mr) ? v0 : 0.f;
            float a1 = (nr + 1 <= mr) ? v1 : 0.f;
            st_h2(d_Abh + co + (size_t)mr*CH + nr, a0, a1);
        })
    }
}

// fused wave3: gprefix (4096 blocks, half2) + den (512 blocks)
__global__ void __launch_bounds__(256) wave3() {
    int bid = blockIdx.x, tid = threadIdx.x;
    if (bid < 4096) {
        size_t idx = (size_t)bid*256 + tid;           // BSZ*DD*DD/2
        const size_t HP = (size_t)DD*DD/2;
        int b = (int)(idx / HP);
        size_t rem = idx % HP;
        const __half2* G2 = (const __half2*)d_Gh;
        __half2* S2 = (__half2*)d_Sph;
        float rx = 0.f, ry = 0.f;
        for (int n = 0; n < NCH; ++n) {
            size_t off = ((size_t)(b*NCH + n))*HP + rem;
            __half2 t = G2[off];
            S2[off] = __floats2half2_rn(rx, ry);
            rx += __low2float(t);
            ry += __high2float(t);
        }
    } else {
        int warp = ((bid - 4096)*256 + tid) >> 5;
        int lane = tid & 31;
        if (warp >= BSZ*NCH*CH) return;
        int bn = warp / CH, i = warp % CH;
        int b = bn >> 4, n = bn & 15;
        const __half2* qr = (const __half2*)(d_sqh + (size_t)(b*SEQ + n*CH + i)*DD);
        const float2* zr = (const float2*)(d_zz + (size_t)bn*DD);
        float s = 0.f;
        for (int k = lane; k < DD/2; k += 32) {
            __half2 h = qr[k]; float2 z = zr[k];
            s += __low2float(h) * z.x + __high2float(h) * z.y;
        }
        const __half2* ar = (const __half2*)(d_Abh + (size_t)bn*CH*CH + (size_t)i*CH);
        for (int j = lane; j < CH/2; j += 32) {
            __half2 h = ar[j];
            s += __low2float(h) + __high2float(h);
        }
        #pragma unroll
        for (int o = 16; o > 0; o >>= 1) s += __shfl_xor_sync(0xffffffffu, s, o);
        if (lane == 0) d_den[warp] = fmaxf(s, EPSV);
    }
}

// attn: local = (sq @ Sp + Abuf @ v)/den; phase2 one-shot; combine fused -> d_cmh
__global__ void __launch_bounds__(256, 2) tc_attn() {
    GEMM_SMEM;
    int tid = threadIdx.x;
    int bn = blockIdx.z; int b = bn >> 4, n = bn & 15;
    size_t cb = (size_t)(b*SEQ + n*CH)*DD;
    int n0 = blockIdx.x * 128;
    float acc[2][8][4] = {};
    {
        Op A{d_sqh + cb, DD};
        Op B{d_Sph + (size_t)bn*DD*DD + n0, DD};
        gemm_core<0,1>(A, B, DD, acc, sm_, tid);
    }
    {
        Op A{d_Abh + (size_t)bn*CH*CH, CH};
        Op B{d_vh + cb + n0, DD};
        gemm_once<0,1>(A, B, acc, sm_, tid);
    }
    float og = 1.f - d_scal[0];
    EPI_COORDS;
    EPI_LOOP2({
        size_t o = cb + (size_t)mr*DD + n0 + nr;
        float inv = og / d_den[bn*CH + mr];
        __half2 m = *(const __half2*)(d_memouth + o);
        st_h2(d_cmh + o, __low2float(m) + v0 * inv, __high2float(m) + v1 * inv);
    })
}

__global__ void __launch_bounds__(256, 2) tc_final(float* __restrict__ Out) {
    GEMM_SMEM;
    int tid = threadIdx.x;
    int m0 = blockIdx.y * 128, n0 = blockIdx.x * 128;
    float acc[2][8][4] = {};
    Op A{d_cmh + (size_t)m0*DD, DD};
    Op B{d_woh + (size_t)n0*DD, DD};
    gemm_core<0,0>(A, B, DD, acc, sm_, tid);
    EPI_COORDS;
    EPI_LOOP2({
        float2 w; w.x = v0; w.y = v1;
        *(float2*)(Out + (size_t)(m0+mr)*DD + n0 + nr) = w;
    })
}

// ---------------- launcher ----------------
extern "C" void kernel_launch(void* const* d_in, const int* in_sizes, int n_in,
                              void* d_out, int out_size) {
    const float* hs    = (const float*)d_in[0];
    const float* wq    = (const float*)d_in[1];
    const float* wk    = (const float*)d_in[2];
    const float* wv    = (const float*)d_in[3];
    const float* wo    = (const float*)d_in[4];
    const float* gate  = (const float*)d_in[5];
    const float* mem   = (const float*)d_in[6];
    const float* mnorm = (const float*)d_in[7];
    float* out = (float*)d_out;

    cudaFuncSetAttribute(tc_proj3, cudaFuncAttributeMaxDynamicSharedMemorySize, SMEM_PIPE);
    cudaFuncSetAttribute(wave2,    cudaFuncAttributeMaxDynamicSharedMemorySize, SMEM_OS);
    cudaFuncSetAttribute(tc_attn,  cudaFuncAttributeMaxDynamicSharedMemorySize, SMEM_OS);
    cudaFuncSetAttribute(tc_final, cudaFuncAttributeMaxDynamicSharedMemorySize, SMEM_PIPE);

    scalars_kernel<<<1, 1024>>>(gate, mnorm);

    cvt_all<<<12288, 256>>>((const float4*)hs, (const float4*)wq, (const float4*)wk,
                            (const float4*)wv, (const float4*)wo, mem);

    dim3 gP(DD/128, MTOT/128, 3);       // (8, 32, 3)
    tc_proj3<<<gP, 256, SMEM_PIPE>>>();

    aux_kernel<<<576, 256>>>(mnorm);    // normq + zc (vectorized)
    zprefix_kernel<<<(BSZ*DD + 255)/256, 256>>>();

    wave2<<<2336, 256, SMEM_OS>>>();
    wave3<<<4608, 256>>>();

    dim3 gAt(DD/128, 1, BSZ*NCH);       // (8, 1, 32)
    tc_attn<<<gAt, 256, SMEM_OS>>>();

    dim3 gM(DD/128, MTOT/128);          // (8, 32)
    tc_final<<<gM, 256, SMEM_PIPE>>>(out);
}